// round 13
// baseline (speedup 1.0000x reference)
#include <cuda_runtime.h>
#include <cuda_bf16.h>
#include <float.h>
#include <stdint.h>

#define NT   8192
#define DM   512
#define NH   8
#define DH   64
#define LM   256
#define ATTD 256
#define CK   33

// ---------------- device scratch ----------------
__device__ float g_qkv[NT * 3 * DM];
__device__ float g_ql[NH * LM * DH];
__device__ float g_kl[NH * LM * DH];
__device__ float g_attn1[(size_t)NH * NT * LM];
__device__ float g_attn3[(size_t)NH * LM * NT];
__device__ float g_attn2[NH * LM * LM];
__device__ float g_t3p[16 * NH * LM * DH];
__device__ float g_outh[NT * DM];
__device__ float g_convres[NT * DM];
__device__ float g_enc [NT * DM];
__device__ float g_q2[NT * ATTD];
__device__ float g_k2[NT * ATTD];
__device__ float g_val[NT * DM];
__device__ float g_Araw[NT];
__device__ float g_alpha[NT];
__device__ float g_rs[NH * LM];
__device__ float g_cs[NH * LM];
__device__ float g_scale[1];
// bf16 buffers
__device__ __nv_bfloat16 g_dh[NT * DM];
__device__ __nv_bfloat16 g_dl[NT * DM];
__device__ __nv_bfloat16 g_th[NT * DM];
__device__ __nv_bfloat16 g_tl[NT * DM];
__device__ __nv_bfloat16 g_ench[NT * DM];
__device__ __nv_bfloat16 g_encl[NT * DM];
__device__ __nv_bfloat16 g_wth[3 * DM * DM];   // qkv_w split
__device__ __nv_bfloat16 g_wtl[3 * DM * DM];
__device__ __nv_bfloat16 g_wvth[DM * DM];
__device__ __nv_bfloat16 g_wvtl[DM * DM];
__device__ __nv_bfloat16 g_woth[DM * DM];      // out_w split
__device__ __nv_bfloat16 g_wotl[DM * DM];
__device__ __nv_bfloat16 g_wqth[DM * ATTD];
__device__ __nv_bfloat16 g_wqtl[DM * ATTD];
__device__ __nv_bfloat16 g_wkth[DM * ATTD];
__device__ __nv_bfloat16 g_wktl[DM * ATTD];
__device__ __nv_bfloat16 g_qkvh[NT * 3 * DM];
__device__ __nv_bfloat16 g_qkvl[NT * 3 * DM];
__device__ __nv_bfloat16 g_a1h[(size_t)NH * NT * LM];
__device__ __nv_bfloat16 g_a1l[(size_t)NH * NT * LM];
__device__ __nv_bfloat16 g_a3h[(size_t)NH * LM * NT];
__device__ __nv_bfloat16 g_a3l[(size_t)NH * LM * NT];
__device__ __nv_bfloat16 g_vth[NH * DH * NT];
__device__ __nv_bfloat16 g_vtl[NH * DH * NT];
__device__ __nv_bfloat16 g_qlh[NH * LM * DH];
__device__ __nv_bfloat16 g_qll[NH * LM * DH];
__device__ __nv_bfloat16 g_klh[NH * LM * DH];
__device__ __nv_bfloat16 g_kll[NH * LM * DH];
__device__ __nv_bfloat16 g_t3th[NH * DH * LM];
__device__ __nv_bfloat16 g_t3tl[NH * DH * LM];
__device__ __nv_bfloat16 g_t4th[NH * DH * LM];
__device__ __nv_bfloat16 g_t4tl[NH * DH * LM];
// pinv bf16 buffers
__device__ __nv_bfloat16 g_a2h[NH * LM * LM];
__device__ __nv_bfloat16 g_a2l[NH * LM * LM];
__device__ __nv_bfloat16 g_zAh[NH * LM * LM];
__device__ __nv_bfloat16 g_zAl[NH * LM * LM];
__device__ __nv_bfloat16 g_zATh[NH * LM * LM];
__device__ __nv_bfloat16 g_zATl[NH * LM * LM];
__device__ __nv_bfloat16 g_zBh[NH * LM * LM];
__device__ __nv_bfloat16 g_zBl[NH * LM * LM];
__device__ __nv_bfloat16 g_zBTh[NH * LM * LM];
__device__ __nv_bfloat16 g_zBTl[NH * LM * LM];
__device__ __nv_bfloat16 g_xzh[NH * LM * LM];
__device__ __nv_bfloat16 g_xzl[NH * LM * LM];
__device__ __nv_bfloat16 g_t1Th[NH * LM * LM];
__device__ __nv_bfloat16 g_t1Tl[NH * LM * LM];
__device__ __nv_bfloat16 g_uTh[NH * LM * LM];
__device__ __nv_bfloat16 g_uTl[NH * LM * LM];
__device__ __nv_bfloat16 g_wTh[NH * LM * LM];
__device__ __nv_bfloat16 g_wTl[NH * LM * LM];

// ---------------- mma.sync / cp.async helpers ----------------
__device__ __forceinline__ uint32_t smem_u32(const void* p) {
    uint32_t a;
    asm("{ .reg .u64 t; cvta.to.shared.u64 t, %1; cvt.u32.u64 %0, t; }" : "=r"(a) : "l"(p));
    return a;
}
__device__ __forceinline__ void ldsm4(uint32_t* r, uint32_t addr) {
    asm volatile("ldmatrix.sync.aligned.m8n8.x4.shared.b16 {%0,%1,%2,%3}, [%4];"
                 : "=r"(r[0]), "=r"(r[1]), "=r"(r[2]), "=r"(r[3]) : "r"(addr));
}
__device__ __forceinline__ void mma16816(float* c, const uint32_t* a, const uint32_t* b) {
    asm volatile(
        "mma.sync.aligned.m16n8k16.row.col.f32.bf16.bf16.f32 "
        "{%0,%1,%2,%3}, {%4,%5,%6,%7}, {%8,%9}, {%0,%1,%2,%3};"
        : "+f"(c[0]), "+f"(c[1]), "+f"(c[2]), "+f"(c[3])
        : "r"(a[0]), "r"(a[1]), "r"(a[2]), "r"(a[3]), "r"(b[0]), "r"(b[1]));
}
__device__ __forceinline__ void cp16(uint32_t s, const void* g) {
    asm volatile("cp.async.cg.shared.global [%0], [%1], 16;" :: "r"(s), "l"(g));
}
#define CP_COMMIT() asm volatile("cp.async.commit_group;" ::: "memory")
#define CP_WAIT1()  asm volatile("cp.async.wait_group 1;" ::: "memory")

// ================= pipelined HMMA GEMM (bf16x3) =================
template<int WN>
__global__ void __launch_bounds__(128*WN) hmma2_k(
    const __nv_bfloat16* __restrict__ Ah, const __nv_bfloat16* __restrict__ Al, int lda, long sA,
    const __nv_bfloat16* __restrict__ Bh, const __nv_bfloat16* __restrict__ Bl, int ldb, long sB,
    float* __restrict__ C, int ldc, long sC,
    int K, float alpha,
    const float* __restrict__ bias, const float* __restrict__ resid,
    __nv_bfloat16* __restrict__ Ph, __nv_bfloat16* __restrict__ Pl, int ldp, long sP,
    __nv_bfloat16* __restrict__ Th, __nv_bfloat16* __restrict__ Tl, int ldt, long sT,
    int pAux, int tAux, float auxc,
    int splitK, long splitPitch)
{
    constexpr int BN = 64 * WN;
    constexpr int THREADS = 128 * WN;
    constexpr int B1 = BN * 80;
    constexpr int STG = 20480 + 2 * B1;
    extern __shared__ char dsm[];
    const uint32_t sb0 = smem_u32(dsm);

    const int tid = threadIdx.x;
    const int wid = tid >> 5, lid = tid & 31;
    const int wm = wid & 3, wn = wid >> 2;
    const int bz = blockIdx.z;
    const int b = bz / splitK, kseg = bz - b * splitK;
    const int Kseg = K / splitK;
    const int m0 = blockIdx.y * 128, n0 = blockIdx.x * BN;

    const __nv_bfloat16* pAh = Ah + (long)b * sA;
    const __nv_bfloat16* pAl = Al + (long)b * sA;
    const __nv_bfloat16* pBh = Bh + (long)b * sB;
    const __nv_bfloat16* pBl = Bl + (long)b * sB;

    float acc[2][8][4];
    #pragma unroll
    for (int i = 0; i < 2; i++)
        #pragma unroll
        for (int j = 0; j < 8; j++)
            #pragma unroll
            for (int q = 0; q < 4; q++) acc[i][j][q] = 0.f;

    auto load = [&](int kc, int st) {
        const uint32_t sb = sb0 + st * STG;
        #pragma unroll
        for (int it = 0; it < 512 / THREADS; it++) {
            int idx = it * THREADS + tid;
            int row = idx >> 2; int cb = (idx & 3) * 16; int ce = (idx & 3) * 8;
            uint32_t so = sb + row * 80 + cb;
            const long ga = (long)(m0 + row) * lda + kc + ce;
            cp16(so,         pAh + ga);
            cp16(so + 10240, pAl + ga);
        }
        #pragma unroll
        for (int it = 0; it < (BN * 4) / THREADS; it++) {
            int idx = it * THREADS + tid;
            int row = idx >> 2; int cb = (idx & 3) * 16; int ce = (idx & 3) * 8;
            uint32_t so = sb + 20480 + row * 80 + cb;
            const long gb = (long)(n0 + row) * ldb + kc + ce;
            cp16(so,      pBh + gb);
            cp16(so + B1, pBl + gb);
        }
    };

    const int k0 = kseg * Kseg;
    const int nch = Kseg / 32;
    load(k0, 0);
    CP_COMMIT();
    for (int c = 0; c < nch; c++) {
        if (c + 1 < nch) load(k0 + (c + 1) * 32, (c + 1) & 1);
        CP_COMMIT();
        CP_WAIT1();
        __syncthreads();
        const uint32_t uAh = sb0 + (c & 1) * STG;
        const uint32_t uAl = uAh + 10240;
        const uint32_t uBh = uAh + 20480;
        const uint32_t uBl = uBh + B1;
        #pragma unroll
        for (int ks = 0; ks < 2; ks++) {
            const int k16 = ks * 16;
            uint32_t ah[2][4], al[2][4];
            #pragma unroll
            for (int mt = 0; mt < 2; mt++) {
                int r = wm * 32 + mt * 16 + (lid & 15);
                int kk = k16 + ((lid >> 4) << 3);
                uint32_t off = (uint32_t)(r * 80 + kk * 2);
                ldsm4(ah[mt], uAh + off);
                ldsm4(al[mt], uAl + off);
            }
            #pragma unroll
            for (int p = 0; p < 4; p++) {
                int r = wn * 64 + p * 16 + ((lid >> 4) << 3) + (lid & 7);
                int kk = k16 + (lid & 8);
                uint32_t off = (uint32_t)(r * 80 + kk * 2);
                uint32_t bh[4], bl[4];
                ldsm4(bh, uBh + off);
                ldsm4(bl, uBl + off);
                #pragma unroll
                for (int mt = 0; mt < 2; mt++) {
                    #pragma unroll
                    for (int s = 0; s < 2; s++) {
                        float* cc = acc[mt][p * 2 + s];
                        mma16816(cc, ah[mt], &bh[2 * s]);
                        mma16816(cc, ah[mt], &bl[2 * s]);
                        mma16816(cc, al[mt], &bh[2 * s]);
                    }
                }
            }
        }
        __syncthreads();
    }

    float* Cb = C ? (splitK > 1 ? C + (long)bz * splitPitch : C + (long)b * sC) : nullptr;
    const int tr = lid >> 2, tc = (lid & 3) * 2;
    #pragma unroll
    for (int mt = 0; mt < 2; mt++)
        #pragma unroll
        for (int nt = 0; nt < 8; nt++) {
            int row = m0 + wm * 32 + mt * 16 + tr;
            int col = n0 + wn * 64 + nt * 8 + tc;
            float vv[2][2] = {{acc[mt][nt][0] * alpha, acc[mt][nt][1] * alpha},
                              {acc[mt][nt][2] * alpha, acc[mt][nt][3] * alpha}};
            if (bias) {
                float2 bb = *(const float2*)(bias + col);
                vv[0][0] += bb.x; vv[0][1] += bb.y; vv[1][0] += bb.x; vv[1][1] += bb.y;
            }
            #pragma unroll
            for (int rr = 0; rr < 2; rr++) {
                int ro = row + rr * 8;
                if (resid) {
                    float2 r2 = *(const float2*)(resid + (long)b * sC + (long)ro * ldc + col);
                    vv[rr][0] += r2.x; vv[rr][1] += r2.y;
                }
                if (Cb) *(float2*)(Cb + (long)ro * ldc + col) = make_float2(vv[rr][0], vv[rr][1]);
                if (Ph) {
                    float p0 = vv[rr][0], p1 = vv[rr][1];
                    if (pAux) {
                        p0 = (ro == col     ? auxc : 0.f) - p0;
                        p1 = (ro == col + 1 ? auxc : 0.f) - p1;
                    }
                    __nv_bfloat16 h0 = __float2bfloat16(p0);
                    __nv_bfloat16 h1 = __float2bfloat16(p1);
                    long off = (long)b * sP + (long)ro * ldp + col;
                    *(__nv_bfloat162*)(Ph + off) = __nv_bfloat162(h0, h1);
                    *(__nv_bfloat162*)(Pl + off) =
                        __nv_bfloat162(__float2bfloat16(p0 - __bfloat162float(h0)),
                                       __float2bfloat16(p1 - __bfloat162float(h1)));
                }
                if (Th) {
                    #pragma unroll
                    for (int cc = 0; cc < 2; cc++) {
                        float tv = vv[rr][cc];
                        if (tAux) tv = (ro == col + cc ? auxc : 0.f) - tv;
                        __nv_bfloat16 hh = __float2bfloat16(tv);
                        long off = (long)b * sT + (long)(col + cc) * ldt + ro;
                        Th[off] = hh;
                        Tl[off] = __float2bfloat16(tv - __bfloat162float(hh));
                    }
                }
            }
        }
}
static const int HS1 = 2 * (20480 + 2 * 64 * 80);    // 61440
static const int HS2 = 2 * (20480 + 2 * 128 * 80);   // 81920

// ---------------- bf16 split prep kernels ----------------
__global__ void split_k(const float* __restrict__ x, __nv_bfloat16* __restrict__ h,
                        __nv_bfloat16* __restrict__ l, int n4)
{
    int i = blockIdx.x * 256 + threadIdx.x;
    if (i >= n4) return;
    float4 v = ((const float4*)x)[i];
    __nv_bfloat16 h0 = __float2bfloat16(v.x), h1 = __float2bfloat16(v.y);
    __nv_bfloat16 h2 = __float2bfloat16(v.z), h3 = __float2bfloat16(v.w);
    __nv_bfloat162* hp = (__nv_bfloat162*)h;
    __nv_bfloat162* lp = (__nv_bfloat162*)l;
    hp[i*2]   = __nv_bfloat162(h0, h1);
    hp[i*2+1] = __nv_bfloat162(h2, h3);
    lp[i*2]   = __nv_bfloat162(__float2bfloat16(v.x - __bfloat162float(h0)),
                               __float2bfloat16(v.y - __bfloat162float(h1)));
    lp[i*2+1] = __nv_bfloat162(__float2bfloat16(v.z - __bfloat162float(h2)),
                               __float2bfloat16(v.w - __bfloat162float(h3)));
}
__global__ void splitT_k(const float* __restrict__ w, __nv_bfloat16* __restrict__ h,
                         __nv_bfloat16* __restrict__ l, int K, int N)
{
    int idx = blockIdx.x * 256 + threadIdx.x;
    if (idx >= N * K) return;
    int n = idx / K, k = idx - n * K;
    float v = w[(long)k * N + n];
    __nv_bfloat16 hb = __float2bfloat16(v);
    h[idx] = hb;
    l[idx] = __float2bfloat16(v - __bfloat162float(hb));
}
__global__ void vT_split_k(const float* __restrict__ qkv,
                           __nv_bfloat16* __restrict__ vh, __nv_bfloat16* __restrict__ vl)
{
    __shared__ float tile[64][65];
    int h = blockIdx.y, n0 = blockIdx.x * 64;
    int tid = threadIdx.x;
    for (int i = tid; i < 64 * 64; i += 256) {
        int r = i >> 6, c = i & 63;
        tile[r][c] = qkv[(long)(n0 + r) * (3*DM) + 2*DM + h * DH + c];
    }
    __syncthreads();
    for (int i = tid; i < 64 * 64; i += 256) {
        int c = i >> 6, r = i & 63;
        float v = tile[r][c];
        __nv_bfloat16 hb = __float2bfloat16(v);
        long off = ((long)h * DH + c) * NT + n0 + r;
        vh[off] = hb;
        vl[off] = __float2bfloat16(v - __bfloat162float(hb));
    }
}
// fused: reduce 16 split-K partials of t3 AND emit transposed bf16 hi/lo
__global__ void reduce_t3T(const float* __restrict__ part,
                           __nv_bfloat16* __restrict__ th, __nv_bfloat16* __restrict__ tl)
{
    int idx = blockIdx.x * 256 + threadIdx.x;
    if (idx >= NH * DH * LM) return;
    int h = idx >> 14, c = (idx >> 8) & 63, m = idx & 255;
    float s = 0.f;
    const float* p = part + ((long)h * 16 << 14) + (m << 6) + c;
    #pragma unroll
    for (int ss = 0; ss < 16; ss++) s += p[(long)ss << 14];
    __nv_bfloat16 hb = __float2bfloat16(s);
    th[idx] = hb;
    tl[idx] = __float2bfloat16(s - __bfloat162float(hb));
}
// z0 = a2^T * s
__global__ void pinv_init2(const float* __restrict__ a2, const float* __restrict__ sc,
                           __nv_bfloat16* __restrict__ zh, __nv_bfloat16* __restrict__ zl,
                           __nv_bfloat16* __restrict__ zth, __nv_bfloat16* __restrict__ ztl)
{
    int idx = blockIdx.x * 256 + threadIdx.x;
    int h = idx >> 16, r = (idx >> 8) & 255, c = idx & 255;
    float s = sc[0];
    float vt = a2[idx] * s;
    float vn = a2[(h << 16) + (c << 8) + r] * s;
    __nv_bfloat16 hn = __float2bfloat16(vn), ht = __float2bfloat16(vt);
    zh[idx] = hn; zl[idx] = __float2bfloat16(vn - __bfloat162float(hn));
    zth[idx] = ht; ztl[idx] = __float2bfloat16(vt - __bfloat162float(ht));
}

// ---------------- f32x2 helpers (SIMT gemm for attn2) ----------------
__device__ __forceinline__ unsigned long long dup2(float x) {
    unsigned long long r;
    asm("mov.b64 %0, {%1, %1};" : "=l"(r) : "f"(x));
    return r;
}
__device__ __forceinline__ void fma2(unsigned long long& d, unsigned long long a, unsigned long long b) {
    asm("fma.rn.f32x2 %0, %1, %2, %0;" : "+l"(d) : "l"(a), "l"(b));
}
__device__ __forceinline__ void unpack2(unsigned long long v, float& lo, float& hi) {
    asm("mov.b64 {%0, %1}, %2;" : "=f"(lo), "=f"(hi) : "l"(v));
}

// ---------------- reductions ----------------
__device__ __forceinline__ float warpSum(float v) {
    #pragma unroll
    for (int o = 16; o; o >>= 1) v += __shfl_xor_sync(0xffffffffu, v, o);
    return v;
}
__device__ __forceinline__ float warpMax(float v) {
    #pragma unroll
    for (int o = 16; o; o >>= 1) v = fmaxf(v, __shfl_xor_sync(0xffffffffu, v, o));
    return v;
}
__device__ float blockSum(float v) {
    __shared__ float sh[33];
    int lane = threadIdx.x & 31, wid = threadIdx.x >> 5;
    v = warpSum(v);
    __syncthreads();
    if (lane == 0) sh[wid] = v;
    __syncthreads();
    int nw = blockDim.x >> 5;
    float r = (wid == 0 && lane < nw) ? sh[lane] : 0.f;
    if (wid == 0) { r = warpSum(r); if (lane == 0) sh[32] = r; }
    __syncthreads();
    return sh[32];
}
__device__ float blockMax(float v) {
    __shared__ float sh[33];
    int lane = threadIdx.x & 31, wid = threadIdx.x >> 5;
    v = warpMax(v);
    __syncthreads();
    if (lane == 0) sh[wid] = v;
    __syncthreads();
    int nw = blockDim.x >> 5;
    float r = (wid == 0 && lane < nw) ? sh[lane] : -FLT_MAX;
    if (wid == 0) { r = warpMax(r); if (lane == 0) sh[32] = r; }
    __syncthreads();
    return sh[32];
}

// ---------------- SIMT GEMM (attn2 only) ----------------
template<int BM, int BN, int BK, int TM, int TN, bool TB>
__global__ __launch_bounds__((BM/TM)*(BN/TN))
void gemm_k(const float* __restrict__ A, int lda, long sA,
            const float* __restrict__ B, int ldb, long sB,
            float* __restrict__ C, int ldc, long sC,
            int K, float alpha)
{
    constexpr int THREADS = (BM/TM)*(BN/TN);
    __shared__ __align__(16) float As[BM][BK + 4];
    __shared__ __align__(16) float Bs[BK][BN + 4];
    const int tid = threadIdx.x;
    const int batch = blockIdx.z;
    const int m0 = blockIdx.y * BM, n0 = blockIdx.x * BN;
    const float* Ab = A + (long)batch * sA + (long)m0 * lda;
    const float* Bb = B + (long)batch * sB;

    unsigned long long acc[TM][TN/2];
    #pragma unroll
    for (int i = 0; i < TM; i++)
        #pragma unroll
        for (int j = 0; j < TN/2; j++) acc[i][j] = 0ull;

    const int tx = tid % (BN/TN), ty = tid / (BN/TN);

    for (int k0 = 0; k0 < K; k0 += BK) {
        #pragma unroll
        for (int idx = tid; idx < BM*(BK/4); idx += THREADS) {
            int m = idx / (BK/4), kq = idx - m * (BK/4);
            float4 v = *(const float4*)(Ab + (long)m * lda + k0 + kq*4);
            *(float4*)&As[m][kq*4] = v;
        }
        if (!TB) {
            #pragma unroll
            for (int idx = tid; idx < BK*(BN/4); idx += THREADS) {
                int kk = idx / (BN/4), nq = idx - kk * (BN/4);
                float4 v = *(const float4*)(Bb + (long)(k0+kk) * ldb + n0 + nq*4);
                *(float4*)&Bs[kk][nq*4] = v;
            }
        } else {
            #pragma unroll
            for (int idx = tid; idx < BN*(BK/4); idx += THREADS) {
                int n = idx / (BK/4), kq = idx - n * (BK/4);
                float4 v = *(const float4*)(Bb + (long)(n0+n) * ldb + k0 + kq*4);
                Bs[kq*4+0][n] = v.x; Bs[kq*4+1][n] = v.y;
                Bs[kq*4+2][n] = v.z; Bs[kq*4+3][n] = v.w;
            }
        }
        __syncthreads();
        #pragma unroll
        for (int kk = 0; kk < BK; kk++) {
            unsigned long long bb[TN/2];
            #pragma unroll
            for (int q = 0; q < TN/4; q++) {
                ulonglong2 bv = *(const ulonglong2*)&Bs[kk][tx*TN + q*4];
                bb[q*2]   = bv.x;
                bb[q*2+1] = bv.y;
            }
            #pragma unroll
            for (int i = 0; i < TM; i++) {
                unsigned long long aa = dup2(As[ty*TM + i][kk]);
                #pragma unroll
                for (int j = 0; j < TN/2; j++) fma2(acc[i][j], aa, bb[j]);
            }
        }
        __syncthreads();
    }

    float* Cb = C + (long)batch * sC;
    #pragma unroll
    for (int i = 0; i < TM; i++) {
        int m = m0 + ty*TM + i;
        #pragma unroll
        for (int j = 0; j < TN/2; j++) {
            float lo, hi;
            unpack2(acc[i][j], lo, hi);
            Cb[(long)m * ldc + n0 + tx*TN + 2*j]     = alpha * lo;
            Cb[(long)m * ldc + n0 + tx*TN + 2*j + 1] = alpha * hi;
        }
    }
}

// ---------------- landmarks ----------------
__global__ void landmarks_k(const float* __restrict__ qkv, float* __restrict__ ql, float* __restrict__ kl,
                            __nv_bfloat16* __restrict__ qlh, __nv_bfloat16* __restrict__ qll,
                            __nv_bfloat16* __restrict__ klh, __nv_bfloat16* __restrict__ kll)
{
    int hm = blockIdx.x;
    int h = hm >> 8, mm = hm & 255;
    int d = threadIdx.x;
    const float* base = qkv + (long)(mm * 32) * (3*DM) + h * DH + d;
    float sq = 0.f, sk = 0.f;
    #pragma unroll 8
    for (int r = 0; r < 32; r++) { sq += base[r * (3*DM)]; sk += base[r * (3*DM) + DM]; }
    float q = sq * (1.f / 32.f) * 0.125f;
    float k = sk * (1.f / 32.f);
    int o = hm * DH + d;
    ql[o] = q; kl[o] = k;
    __nv_bfloat16 qh = __float2bfloat16(q), kh = __float2bfloat16(k);
    qlh[o] = qh; qll[o] = __float2bfloat16(q - __bfloat162float(qh));
    klh[o] = kh; kll[o] = __float2bfloat16(k - __bfloat162float(kh));
}

// ---------------- softmaxes ----------------
__device__ __forceinline__ void store_split4(__nv_bfloat16* ph, __nv_bfloat16* pl, float4 v)
{
    __nv_bfloat16 h0 = __float2bfloat16(v.x), h1 = __float2bfloat16(v.y);
    __nv_bfloat16 h2 = __float2bfloat16(v.z), h3 = __float2bfloat16(v.w);
    *(__nv_bfloat162*)ph = __nv_bfloat162(h0, h1);
    *(__nv_bfloat162*)(ph+2) = __nv_bfloat162(h2, h3);
    *(__nv_bfloat162*)pl = __nv_bfloat162(__float2bfloat16(v.x - __bfloat162float(h0)),
                                          __float2bfloat16(v.y - __bfloat162float(h1)));
    *(__nv_bfloat162*)(pl+2) = __nv_bfloat162(__float2bfloat16(v.z - __bfloat162float(h2)),
                                              __float2bfloat16(v.w - __bfloat162float(h3)));
}

__global__ void softmax256(float* __restrict__ d, __nv_bfloat16* __restrict__ oh, __nv_bfloat16* __restrict__ ol)
{
    int warp = threadIdx.x >> 5, lane = threadIdx.x & 31;
    long row = (long)blockIdx.x * 8 + warp;
    float* p = d + row * 256;
    float4 v0 = *(float4*)(p + lane*4);
    float4 v1 = *(float4*)(p + 128 + lane*4);
    float mx = fmaxf(fmaxf(fmaxf(v0.x, v0.y), fmaxf(v0.z, v0.w)),
                     fmaxf(fmaxf(v1.x, v1.y), fmaxf(v1.z, v1.w)));
    mx = warpMax(mx);
    v0.x = __expf(v0.x - mx); v0.y = __expf(v0.y - mx);
    v0.z = __expf(v0.z - mx); v0.w = __expf(v0.w - mx);
    v1.x = __expf(v1.x - mx); v1.y = __expf(v1.y - mx);
    v1.z = __expf(v1.z - mx); v1.w = __expf(v1.w - mx);
    float s = v0.x + v0.y + v0.z + v0.w + v1.x + v1.y + v1.z + v1.w;
    s = warpSum(s);
    float inv = 1.f / s;
    v0.x *= inv; v0.y *= inv; v0.z *= inv; v0.w *= inv;
    v1.x *= inv; v1.y *= inv; v1.z *= inv; v1.w *= inv;
    if (oh) {
        store_split4(oh + row*256 + lane*4, ol + row*256 + lane*4, v0);
        store_split4(oh + row*256 + 128 + lane*4, ol + row*256 + 128 + lane*4, v1);
    } else {
        *(float4*)(p + lane*4) = v0;
        *(float4*)(p + 128 + lane*4) = v1;
    }
}

__global__ __launch_bounds__(256)
void softmax8192(float* __restrict__ d, __nv_bfloat16* __restrict__ oh, __nv_bfloat16* __restrict__ ol)
{
    long rb = (long)blockIdx.x * 8192;
    float* p = d + rb;
    int t = threadIdx.x;
    float4 v[8];
    float mx = -FLT_MAX;
    #pragma unroll
    for (int q = 0; q < 8; q++) {
        v[q] = *(float4*)(p + (q*256 + t)*4);
        mx = fmaxf(mx, fmaxf(fmaxf(v[q].x, v[q].y), fmaxf(v[q].z, v[q].w)));
    }
    mx = blockMax(mx);
    float s = 0.f;
    #pragma unroll
    for (int q = 0; q < 8; q++) {
        v[q].x = __expf(v[q].x - mx); v[q].y = __expf(v[q].y - mx);
        v[q].z = __expf(v[q].z - mx); v[q].w = __expf(v[q].w - mx);
        s += v[q].x + v[q].y + v[q].z + v[q].w;
    }
    s = blockSum(s);
    float inv = 1.f / s;
    #pragma unroll
    for (int q = 0; q < 8; q++) {
        v[q].x *= inv; v[q].y *= inv; v[q].z *= inv; v[q].w *= inv;
        store_split4(oh + rb + (q*256 + t)*4, ol + rb + (q*256 + t)*4, v[q]);
    }
}

// ---------------- pinv scale helpers ----------------
__global__ void absmax_sums(const float* __restrict__ x, float* __restrict__ rs, float* __restrict__ cs)
{
    int h = blockIdx.x, t = threadIdx.x;
    const float* base = x + (long)h * LM * LM;
    float r = 0.f;
    const float* rp = base + (long)t * LM;
    #pragma unroll 8
    for (int i = 0; i < LM; i++) r += fabsf(rp[i]);
    rs[h * LM + t] = r;
    float c = 0.f;
    const float* cp = base + t;
    #pragma unroll 8
    for (int i = 0; i < LM; i++) c += fabsf(cp[i * LM]);
    cs[h * LM + t] = c;
}
__global__ void calc_scale(const float* __restrict__ rs, const float* __restrict__ cs, float* __restrict__ sc)
{
    float mr = -FLT_MAX, mc = -FLT_MAX;
    for (int i = threadIdx.x; i < NH * LM; i += blockDim.x) {
        mr = fmaxf(mr, rs[i]); mc = fmaxf(mc, cs[i]);
    }
    mr = blockMax(mr); mc = blockMax(mc);
    if (threadIdx.x == 0) sc[0] = 1.f / (mr * mc);
}

// ---------------- depthwise conv (standalone result buffer) ----------------
__global__ void conv_store_k(const float* __restrict__ qkv, const float* __restrict__ cw,
                             float* __restrict__ convres)
{
    __shared__ float ws[NH * CK];
    for (int t = threadIdx.x; t < NH * CK; t += blockDim.x) ws[t] = cw[t];
    __syncthreads();
    int idx = blockIdx.x * blockDim.x + threadIdx.x;
    if (idx >= NT * DM) return;
    int c = idx & (DM - 1);
    int n = idx >> 9;
    int h = c >> 6;
    const float* wrow = ws + h * CK;
    float acc = 0.f;
    #pragma unroll
    for (int k = 0; k < CK; k++) {
        int nn = n - (CK/2) + k;
        if (nn >= 0 && nn < NT) acc += wrow[k] * qkv[(long)nn * (3*DM) + 2*DM + c];
    }
    convres[idx] = acc;
}

// ---------------- A_raw ----------------
__global__ void araw_k(const float* __restrict__ adj, const float* __restrict__ q2,
                       const float* __restrict__ k2, float* __restrict__ Araw)
{
    int i = blockIdx.x;
    __shared__ float qs[ATTD];
    qs[threadIdx.x] = q2[(long)i * ATTD + threadIdx.x];
    __syncthreads();
    float acc = 0.f;
    const float4* arow = (const float4*)(adj + (long)i * NT);
    const float4* q4 = (const float4*)qs;
    for (int t = threadIdx.x; t < NT/4; t += blockDim.x) {
        float4 a4 = arow[t];
        float av[4] = {a4.x, a4.y, a4.z, a4.w};
        #pragma unroll
        for (int c = 0; c < 4; c++) {
            if (av[c] != 0.f) {
                int j = t * 4 + c;
                const float4* k4 = (const float4*)(k2 + (long)j * ATTD);
                float dot = 0.f;
                #pragma unroll 8
                for (int d = 0; d < ATTD/4; d++) {
                    float4 a = q4[d], b = k4[d];
                    dot += a.x*b.x + a.y*b.y + a.z*b.z + a.w*b.w;
                }
                acc += av[c] * dot;
            }
        }
    }
    acc = blockSum(acc);
    if (threadIdx.x == 0) Araw[i] = acc * (1.f / 16.f);
}

__global__ void alpha_softmax_k(const float* __restrict__ Araw, float* __restrict__ alpha)
{
    float mx = -FLT_MAX;
    for (int i = threadIdx.x; i < NT; i += blockDim.x) mx = fmaxf(mx, Araw[i]);
    mx = blockMax(mx);
    float s = 0.f;
    for (int i = threadIdx.x; i < NT; i += blockDim.x) {
        float e = __expf(Araw[i] - mx); alpha[i] = e; s += e;
    }
    s = blockSum(s);
    float inv = 1.f / s;
    for (int i = threadIdx.x; i < NT; i += blockDim.x) alpha[i] *= inv;
}

// ---------------- final elementwise ----------------
__global__ void final_k(const float* __restrict__ val, const float* __restrict__ enc,
                        const float* __restrict__ alpha, const float* __restrict__ Araw,
                        float* __restrict__ out)
{
    int idx = blockIdx.x * blockDim.x + threadIdx.x;
    if (idx >= NT * DM) return;
    int n = idx >> 9;
    float xl = alpha[n] * val[idx];
    float wei = 1.f / (1.f + __expf(xl));
    float sq = wei * wei;
    out[idx] = xl * 2.f * sq + 2.f * enc[idx] * (1.f - sq);
    if (idx < NT) out[(long)NT * DM + idx] = Araw[idx];
}

// ---------------- host ----------------
#define GEMM_MED_T gemm_k<64,64,16,4,4,true>
#define NB16 (__nv_bfloat16*)nullptr
#define F32N (float*)nullptr

// Streams/events created exactly once on first call (correctness run, before the
// harness's pre-capture memory baseline); reused every call thereafter.
struct SideCtx {
    cudaStream_t s1, s2;
    cudaEvent_t evStart, ev0, evW, evQkv, evLm, evZ, evVal, evConv, evVT, evEnc, evK2;
    SideCtx() {
        cudaStreamCreateWithFlags(&s1, cudaStreamNonBlocking);
        cudaStreamCreateWithFlags(&s2, cudaStreamNonBlocking);
        cudaEventCreateWithFlags(&evStart, cudaEventDisableTiming);
        cudaEventCreateWithFlags(&ev0, cudaEventDisableTiming);
        cudaEventCreateWithFlags(&evW, cudaEventDisableTiming);
        cudaEventCreateWithFlags(&evQkv, cudaEventDisableTiming);
        cudaEventCreateWithFlags(&evLm, cudaEventDisableTiming);
        cudaEventCreateWithFlags(&evZ, cudaEventDisableTiming);
        cudaEventCreateWithFlags(&evVal, cudaEventDisableTiming);
        cudaEventCreateWithFlags(&evConv, cudaEventDisableTiming);
        cudaEventCreateWithFlags(&evVT, cudaEventDisableTiming);
        cudaEventCreateWithFlags(&evEnc, cudaEventDisableTiming);
        cudaEventCreateWithFlags(&evK2, cudaEventDisableTiming);
    }
};

extern "C" void kernel_launch(void* const* d_in, const int* in_sizes, int n_in,
                              void* d_out, int out_size)
{
    static SideCtx ctx;
    cudaStream_t s1 = ctx.s1, s2 = ctx.s2;

    const float* dense = (const float*)d_in[0];
    const float* adj   = (const float*)d_in[1];
    const float* wq    = (const float*)d_in[2];
    const float* wk    = (const float*)d_in[3];
    const float* wv_w  = (const float*)d_in[4];
    const float* wv_b  = (const float*)d_in[5];
    const float* qkv_w = (const float*)d_in[6];
    const float* out_w = (const float*)d_in[7];
    const float* out_b = (const float*)d_in[8];
    const float* conv_w= (const float*)d_in[9];
    float* out = (float*)d_out;

    float *qkv, *ql, *kl, *a1, *a3, *a2, *t3p, *outh, *convres, *enc, *q2, *k2, *val;
    float *Araw, *alpha, *rs, *cs, *sc;
    __nv_bfloat16 *dh, *dl, *th, *tl, *ench, *encl, *wth, *wtl, *wvth, *wvtl;
    __nv_bfloat16 *woth, *wotl, *wqth, *wqtl, *wkth, *wktl, *qkvh, *qkvl;
    __nv_bfloat16 *a1h, *a1l, *a3h, *a3l, *vth, *vtl, *qlh, *qll, *klh, *kll;
    __nv_bfloat16 *t3th, *t3tl, *t4th, *t4tl;
    __nv_bfloat16 *a2h, *a2l, *zAh, *zAl, *zATh, *zATl, *zBh, *zBl, *zBTh, *zBTl;
    __nv_bfloat16 *xzh, *xzl, *t1Th, *t1Tl, *uTh, *uTl, *wTh, *wTl;
    cudaGetSymbolAddress((void**)&qkv, g_qkv);
    cudaGetSymbolAddress((void**)&ql, g_ql);
    cudaGetSymbolAddress((void**)&kl, g_kl);
    cudaGetSymbolAddress((void**)&a1, g_attn1);
    cudaGetSymbolAddress((void**)&a3, g_attn3);
    cudaGetSymbolAddress((void**)&a2, g_attn2);
    cudaGetSymbolAddress((void**)&t3p, g_t3p);
    cudaGetSymbolAddress((void**)&outh, g_outh);
    cudaGetSymbolAddress((void**)&convres, g_convres);
    cudaGetSymbolAddress((void**)&enc, g_enc);
    cudaGetSymbolAddress((void**)&q2, g_q2);
    cudaGetSymbolAddress((void**)&k2, g_k2);
    cudaGetSymbolAddress((void**)&val, g_val);
    cudaGetSymbolAddress((void**)&Araw, g_Araw);
    cudaGetSymbolAddress((void**)&alpha, g_alpha);
    cudaGetSymbolAddress((void**)&rs, g_rs);
    cudaGetSymbolAddress((void**)&cs, g_cs);
    cudaGetSymbolAddress((void**)&sc, g_scale);
    cudaGetSymbolAddress((void**)&dh, g_dh);
    cudaGetSymbolAddress((void**)&dl, g_dl);
    cudaGetSymbolAddress((void**)&th, g_th);
    cudaGetSymbolAddress((void**)&tl, g_tl);
    cudaGetSymbolAddress((void**)&ench, g_ench);
    cudaGetSymbolAddress((void**)&encl, g_encl);
    cudaGetSymbolAddress((void**)&wth, g_wth);
    cudaGetSymbolAddress((void**)&wtl, g_wtl);
    cudaGetSymbolAddress((void**)&wvth, g_wvth);
    cudaGetSymbolAddress((void**)&wvtl, g_wvtl);
    cudaGetSymbolAddress((void**)&woth, g_woth);
    cudaGetSymbolAddress((void**)&wotl, g_wotl);
    cudaGetSymbolAddress((void**)&wqth, g_wqth);
    cudaGetSymbolAddress((void**)&wqtl, g_wqtl);
    cudaGetSymbolAddress((void**)&wkth, g_wkth);
    cudaGetSymbolAddress((void**)&wktl, g_wktl);
    cudaGetSymbolAddress((void**)&qkvh, g_qkvh);
    cudaGetSymbolAddress((void**)&qkvl, g_qkvl);
    cudaGetSymbolAddress((void**)&a1h, g_a1h);
    cudaGetSymbolAddress((void**)&a1l, g_a1l);
    cudaGetSymbolAddress((void**)&a3h, g_a3h);
    cudaGetSymbolAddress((void**)&a3l, g_a3l);
    cudaGetSymbolAddress((void**)&vth, g_vth);
    cudaGetSymbolAddress((void**)&vtl, g_vtl);
    cudaGetSymbolAddress((void**)&qlh, g_qlh);
    cudaGetSymbolAddress((void**)&qll, g_qll);
    cudaGetSymbolAddress((void**)&klh, g_klh);
    cudaGetSymbolAddress((void**)&kll, g_kll);
    cudaGetSymbolAddress((void**)&t3th, g_t3th);
    cudaGetSymbolAddress((void**)&t3tl, g_t3tl);
    cudaGetSymbolAddress((void**)&t4th, g_t4th);
    cudaGetSymbolAddress((void**)&t4tl, g_t4tl);
    cudaGetSymbolAddress((void**)&a2h, g_a2h);
    cudaGetSymbolAddress((void**)&a2l, g_a2l);
    cudaGetSymbolAddress((void**)&zAh, g_zAh);
    cudaGetSymbolAddress((void**)&zAl, g_zAl);
    cudaGetSymbolAddress((void**)&zATh, g_zATh);
    cudaGetSymbolAddress((void**)&zATl, g_zATl);
    cudaGetSymbolAddress((void**)&zBh, g_zBh);
    cudaGetSymbolAddress((void**)&zBl, g_zBl);
    cudaGetSymbolAddress((void**)&zBTh, g_zBTh);
    cudaGetSymbolAddress((void**)&zBTl, g_zBTl);
    cudaGetSymbolAddress((void**)&xzh, g_xzh);
    cudaGetSymbolAddress((void**)&xzl, g_xzl);
    cudaGetSymbolAddress((void**)&t1Th, g_t1Th);
    cudaGetSymbolAddress((void**)&t1Tl, g_t1Tl);
    cudaGetSymbolAddress((void**)&uTh, g_uTh);
    cudaGetSymbolAddress((void**)&uTl, g_uTl);
    cudaGetSymbolAddress((void**)&wTh, g_wTh);
    cudaGetSymbolAddress((void**)&wTl, g_wTl);

    cudaFuncSetAttribute(hmma2_k<1>, cudaFuncAttributeMaxDynamicSharedMemorySize, HS1);
    cudaFuncSetAttribute(hmma2_k<2>, cudaFuncAttributeMaxDynamicSharedMemorySize, HS2);

    const long HL = (long)LM * LM;

    // fork point: both side streams join the capture graph via this event
    cudaEventRecord(ctx.evStart, 0);
    cudaStreamWaitEvent(s1, ctx.evStart, 0);
    cudaStreamWaitEvent(s2, ctx.evStart, 0);

    // --- s1 head: input-only weight splits (out_w, wq, wk) ---
    splitT_k<<<(DM*DM + 255)/256, 256, 0, s1>>>(out_w, woth, wotl, DM, DM);
    splitT_k<<<(DM*ATTD + 255)/256, 256, 0, s1>>>(wq, wqth, wqtl, DM, ATTD);
    splitT_k<<<(DM*ATTD + 255)/256, 256, 0, s1>>>(wk, wkth, wktl, DM, ATTD);
    cudaEventRecord(ctx.evW, s1);

    // --- s2 head: wv split (input-only) ---
    splitT_k<<<(DM*DM + 255)/256, 256, 0, s2>>>(wv_w, wvth, wvtl, DM, DM);

    // 1. split dense (main); s2 then runs val GEMM
    split_k<<<(NT*DM/4 + 255)/256, 256>>>(dense, dh, dl, NT*DM/4);
    cudaEventRecord(ctx.ev0, 0);
    cudaStreamWaitEvent(s2, ctx.ev0, 0);
    hmma2_k<2><<<dim3(4, 64, 1), 256, HS2, s2>>>(dh, dl, DM, 0, wvth, wvtl, DM, 0,
        val, DM, 0, DM, 1.f, wv_b, nullptr, NB16, NB16, 0, 0, NB16, NB16, 0, 0, 0, 0, 0.f, 1, 0);
    cudaEventRecord(ctx.evVal, s2);

    // main: qkv = dense @ qkv_w
    splitT_k<<<(3*DM*DM + 255)/256, 256>>>(qkv_w, wth, wtl, DM, 3*DM);
    hmma2_k<2><<<dim3(12, 64, 1), 256, HS2>>>(dh, dl, DM, 0, wth, wtl, DM, 0,
        qkv, 3*DM, 0, DM, 1.f, nullptr, nullptr,
        qkvh, qkvl, 3*DM, 0, NB16, NB16, 0, 0, 0, 0, 0.f, 1, 0);
    cudaEventRecord(ctx.evQkv, 0);

    // s2 (after qkv): vT split + depthwise conv into convres
    cudaStreamWaitEvent(s2, ctx.evQkv, 0);
    vT_split_k<<<dim3(NT/64, NH), 256, 0, s2>>>(qkv, vth, vtl);
    cudaEventRecord(ctx.evVT, s2);
    conv_store_k<<<(NT*DM + 255)/256, 256, 0, s2>>>(qkv, conv_w, convres);
    cudaEventRecord(ctx.evConv, s2);

    // 2. landmarks; fork s1 for the pinv chain
    landmarks_k<<<NH*LM, DH>>>(qkv, ql, kl, qlh, qll, klh, kll);
    cudaEventRecord(ctx.evLm, 0);
    cudaStreamWaitEvent(s1, ctx.evLm, 0);

    // --- s1: attn2 + pinv Newton-Schulz ---
    GEMM_MED_T<<<dim3(LM/64, LM/64, NH), 256, 0, s1>>>(
        ql, DH, (long)LM*DH, kl, DH, (long)LM*DH, a2, LM, HL, DH, 1.f);
    softmax256<<<NH*LM/8, 256, 0, s1>>>(a2, nullptr, nullptr);
    absmax_sums<<<NH, 256, 0, s1>>>(a2, rs, cs);
    calc_scale<<<1, 256, 0, s1>>>(rs, cs, sc);
    split_k<<<NH*LM*LM/4/256, 256, 0, s1>>>(a2, a2h, a2l, NH*LM*LM/4);
    pinv_init2<<<NH*LM*LM/256, 256, 0, s1>>>(a2, sc, zAh, zAl, zATh, zATl);

    __nv_bfloat16 *zinh = zAh, *zinl = zAl, *zinTh = zATh, *zinTl = zATl;
    __nv_bfloat16 *zoth = zBh, *zotl = zBl, *zotTh = zBTh, *zotTl = zBTl;
    const dim3 pgrid(4, 2, NH);
    for (int it = 0; it < 6; it++) {
        hmma2_k<1><<<pgrid, 128, HS1, s1>>>(a2h, a2l, LM, HL, zinTh, zinTl, LM, HL,
            F32N, 0, 0, LM, 1.f, nullptr, nullptr,
            xzh, xzl, LM, HL, t1Th, t1Tl, LM, HL, 0, 1, 7.f, 1, 0);
        hmma2_k<1><<<pgrid, 128, HS1, s1>>>(xzh, xzl, LM, HL, t1Th, t1Tl, LM, HL,
            F32N, 0, 0, LM, 1.f, nullptr, nullptr,
            NB16, NB16, 0, 0, uTh, uTl, LM, HL, 0, 1, 15.f, 1, 0);
        hmma2_k<1><<<pgrid, 128, HS1, s1>>>(xzh, xzl, LM, HL, uTh, uTl, LM, HL,
            F32N, 0, 0, LM, 1.f, nullptr, nullptr,
            NB16, NB16, 0, 0, wTh, wTl, LM, HL, 0, 1, 13.f, 1, 0);
        hmma2_k<1><<<pgrid, 128, HS1, s1>>>(zinh, zinl, LM, HL, wTh, wTl, LM, HL,
            F32N, 0, 0, LM, 0.25f, nullptr, nullptr,
            zoth, zotl, LM, HL, zotTh, zotTl, LM, HL, 0, 0, 0.f, 1, 0);
        __nv_bfloat16* t;
        t = zinh; zinh = zoth; zoth = t;   t = zinl; zinl = zotl; zotl = t;
        t = zinTh; zinTh = zotTh; zotTh = t; t = zinTl; zinTl = zotTl; zotTl = t;
    }
    cudaEventRecord(ctx.evZ, s1);

    // --- main stream: attention chain ---
    // 3. attn1 logits
    hmma2_k<2><<<dim3(2, 64, NH), 256, HS2>>>(qkvh, qkvl, 3*DM, DH, klh, kll, DH, (long)LM*DH,
        a1, LM, (long)NT*LM, DH, 0.125f, nullptr, nullptr,
        NB16, NB16, 0, 0, NB16, NB16, 0, 0, 0, 0, 0.f, 1, 0);
    softmax256<<<NH*NT/8, 256>>>(a1, a1h, a1l);

    // 5. attn3 logits
    hmma2_k<2><<<dim3(64, 2, NH), 256, HS2>>>(qlh, qll, DH, (long)LM*DH, qkvh + DM, qkvl + DM, 3*DM, DH,
        a3, NT, (long)LM*NT, DH, 1.f, nullptr, nullptr,
        NB16, NB16, 0, 0, NB16, NB16, 0, 0, 0, 0, 0.f, 1, 0);
    softmax8192<<<NH*LM, 256>>>(a3, a3h, a3l);

    // 8. t3 = attn3 @ v  (split-K=16); vT from s2
    cudaStreamWaitEvent(0, ctx.evVT, 0);
    hmma2_k<1><<<dim3(1, 2, NH*16), 128, HS1>>>(a3h, a3l, NT, (long)LM*NT, vth, vtl, NT, (long)DH*NT,
        t3p, DH, 0, NT, 1.f, nullptr, nullptr,
        NB16, NB16, 0, 0, NB16, NB16, 0, 0, 0, 0, 0.f, 16, (long)LM*DH);
    reduce_t3T<<<(NH*DH*LM + 255)/256, 256>>>(t3p, t3th, t3tl);

    // join pinv
    cudaStreamWaitEvent(0, ctx.evZ, 0);

    // 9. t4 = pinv @ t3
    hmma2_k<1><<<dim3(1, 2, NH), 128, HS1>>>(zinh, zinl, LM, HL, t3th, t3tl, LM, (long)DH*LM,
        F32N, 0, 0, LM, 1.f, nullptr, nullptr,
        NB16, NB16, 0, 0, t4th, t4tl, LM, (long)DH*LM, 0, 0, 0.f, 1, 0);

    // 10. outh = attn1 @ t4 + convres (resid epilogue; conv from s2)
    cudaStreamWaitEvent(0, ctx.evConv, 0);
    hmma2_k<1><<<dim3(1, 64, NH), 128, HS1>>>(a1h, a1l, LM, (long)NT*LM, t4th, t4tl, LM, (long)DH*LM,
        outh, DM, DH, LM, 1.f, nullptr, convres,
        NB16, NB16, 0, 0, NB16, NB16, 0, 0, 0, 0, 0.f, 1, 0);

    // 12. enc = outh @ out_w + out_b + dense ; emits bf16 hi/lo to ench/encl
    split_k<<<(NT*DM/4 + 255)/256, 256>>>(outh, th, tl, NT*DM/4);
    cudaStreamWaitEvent(0, ctx.evW, 0);
    hmma2_k<2><<<dim3(4, 64, 1), 256, HS2>>>(th, tl, DM, 0, woth, wotl, DM, 0,
        enc, DM, 0, DM, 1.f, out_b, dense, ench, encl, DM, 0, NB16, NB16, 0, 0, 0, 0, 0.f, 1, 0);
    cudaEventRecord(ctx.evEnc, 0);

    // 13. q2 (main) ; k2 (s2, concurrent). enc bf16 in ench/encl.
    cudaStreamWaitEvent(s2, ctx.evEnc, 0);
    hmma2_k<2><<<dim3(2, 64, 1), 256, HS2, s2>>>(ench, encl, DM, 0, wkth, wktl, DM, 0,
        k2, ATTD, 0, DM, 1.f, nullptr, nullptr, NB16, NB16, 0, 0, NB16, NB16, 0, 0, 0, 0, 0.f, 1, 0);
    cudaEventRecord(ctx.evK2, s2);
    hmma2_k<2><<<dim3(2, 64, 1), 256, HS2>>>(ench, encl, DM, 0, wqth, wqtl, DM, 0,
        q2, ATTD, 0, DM, 1.f, nullptr, nullptr, NB16, NB16, 0, 0, NB16, NB16, 0, 0, 0, 0, 0.f, 1, 0);

    // 15. A_raw
    cudaStreamWaitEvent(0, ctx.evK2, 0);
    araw_k<<<NT, 256>>>(adj, q2, k2, Araw);

    // 16. alpha = softmax(A_raw)
    alpha_softmax_k<<<1, 1024>>>(Araw, alpha);

    // 17. final
    cudaStreamWaitEvent(0, ctx.evVal, 0);
    final_k<<<(NT*DM + 255)/256, 256>>>(val, enc, alpha, Araw, out);
}

// round 16
// speedup vs baseline: 1.0177x; 1.0177x over previous
#include <cuda_runtime.h>
#include <cuda_bf16.h>
#include <float.h>
#include <stdint.h>

#define NT   8192
#define DM   512
#define NH   8
#define DH   64
#define LM   256
#define ATTD 256
#define CK   33

// ---------------- device scratch ----------------
__device__ float g_qkv[NT * 3 * DM];
__device__ float g_ql[NH * LM * DH];
__device__ float g_kl[NH * LM * DH];
__device__ float g_attn1[(size_t)NH * NT * LM];
__device__ float g_attn3[(size_t)NH * LM * NT];
__device__ float g_attn2[NH * LM * LM];
__device__ float g_t3p[16 * NH * LM * DH];
__device__ float g_convres[NT * DM];
__device__ float g_enc [NT * DM];
__device__ float g_q2[NT * ATTD];
__device__ float g_k2[NT * ATTD];
__device__ float g_val[NT * DM];
__device__ float g_Araw[NT];
__device__ float g_alpha[NT];
__device__ float g_rs[NH * LM];
__device__ float g_cs[NH * LM];
__device__ float g_scale[1];
// bf16 buffers
__device__ __nv_bfloat16 g_dh[NT * DM];
__device__ __nv_bfloat16 g_dl[NT * DM];
__device__ __nv_bfloat16 g_th[NT * DM];
__device__ __nv_bfloat16 g_tl[NT * DM];
__device__ __nv_bfloat16 g_ench[NT * DM];
__device__ __nv_bfloat16 g_encl[NT * DM];
__device__ __nv_bfloat16 g_wth[3 * DM * DM];   // qkv_w split
__device__ __nv_bfloat16 g_wtl[3 * DM * DM];
__device__ __nv_bfloat16 g_wvth[DM * DM];
__device__ __nv_bfloat16 g_wvtl[DM * DM];
__device__ __nv_bfloat16 g_woth[DM * DM];      // out_w split
__device__ __nv_bfloat16 g_wotl[DM * DM];
__device__ __nv_bfloat16 g_wqth[DM * ATTD];
__device__ __nv_bfloat16 g_wqtl[DM * ATTD];
__device__ __nv_bfloat16 g_wkth[DM * ATTD];
__device__ __nv_bfloat16 g_wktl[DM * ATTD];
__device__ __nv_bfloat16 g_qkvh[NT * 3 * DM];
__device__ __nv_bfloat16 g_qkvl[NT * 3 * DM];
__device__ __nv_bfloat16 g_a1h[(size_t)NH * NT * LM];
__device__ __nv_bfloat16 g_a1l[(size_t)NH * NT * LM];
__device__ __nv_bfloat16 g_a3h[(size_t)NH * LM * NT];
__device__ __nv_bfloat16 g_a3l[(size_t)NH * LM * NT];
__device__ __nv_bfloat16 g_vth[NH * DH * NT];
__device__ __nv_bfloat16 g_vtl[NH * DH * NT];
__device__ __nv_bfloat16 g_qlh[NH * LM * DH];
__device__ __nv_bfloat16 g_qll[NH * LM * DH];
__device__ __nv_bfloat16 g_klh[NH * LM * DH];
__device__ __nv_bfloat16 g_kll[NH * LM * DH];
__device__ __nv_bfloat16 g_t3th[NH * DH * LM];
__device__ __nv_bfloat16 g_t3tl[NH * DH * LM];
__device__ __nv_bfloat16 g_t4th[NH * DH * LM];
__device__ __nv_bfloat16 g_t4tl[NH * DH * LM];
// pinv bf16 buffers
__device__ __nv_bfloat16 g_a2h[NH * LM * LM];
__device__ __nv_bfloat16 g_a2l[NH * LM * LM];
__device__ __nv_bfloat16 g_zAh[NH * LM * LM];
__device__ __nv_bfloat16 g_zAl[NH * LM * LM];
__device__ __nv_bfloat16 g_zATh[NH * LM * LM];
__device__ __nv_bfloat16 g_zATl[NH * LM * LM];
__device__ __nv_bfloat16 g_zBh[NH * LM * LM];
__device__ __nv_bfloat16 g_zBl[NH * LM * LM];
__device__ __nv_bfloat16 g_zBTh[NH * LM * LM];
__device__ __nv_bfloat16 g_zBTl[NH * LM * LM];
__device__ __nv_bfloat16 g_xzh[NH * LM * LM];
__device__ __nv_bfloat16 g_xzl[NH * LM * LM];
__device__ __nv_bfloat16 g_t1Th[NH * LM * LM];
__device__ __nv_bfloat16 g_t1Tl[NH * LM * LM];
__device__ __nv_bfloat16 g_uTh[NH * LM * LM];
__device__ __nv_bfloat16 g_uTl[NH * LM * LM];
__device__ __nv_bfloat16 g_wTh[NH * LM * LM];
__device__ __nv_bfloat16 g_wTl[NH * LM * LM];

// ---------------- mma.sync / cp.async helpers ----------------
__device__ __forceinline__ uint32_t smem_u32(const void* p) {
    uint32_t a;
    asm("{ .reg .u64 t; cvta.to.shared.u64 t, %1; cvt.u32.u64 %0, t; }" : "=r"(a) : "l"(p));
    return a;
}
__device__ __forceinline__ void ldsm4(uint32_t* r, uint32_t addr) {
    asm volatile("ldmatrix.sync.aligned.m8n8.x4.shared.b16 {%0,%1,%2,%3}, [%4];"
                 : "=r"(r[0]), "=r"(r[1]), "=r"(r[2]), "=r"(r[3]) : "r"(addr));
}
__device__ __forceinline__ void mma16816(float* c, const uint32_t* a, const uint32_t* b) {
    asm volatile(
        "mma.sync.aligned.m16n8k16.row.col.f32.bf16.bf16.f32 "
        "{%0,%1,%2,%3}, {%4,%5,%6,%7}, {%8,%9}, {%0,%1,%2,%3};"
        : "+f"(c[0]), "+f"(c[1]), "+f"(c[2]), "+f"(c[3])
        : "r"(a[0]), "r"(a[1]), "r"(a[2]), "r"(a[3]), "r"(b[0]), "r"(b[1]));
}
__device__ __forceinline__ void cp16(uint32_t s, const void* g) {
    asm volatile("cp.async.cg.shared.global [%0], [%1], 16;" :: "r"(s), "l"(g));
}
#define CP_COMMIT() asm volatile("cp.async.commit_group;" ::: "memory")
#define CP_WAIT1()  asm volatile("cp.async.wait_group 1;" ::: "memory")

// ================= pipelined HMMA GEMM (bf16x3) =================
template<int WN>
__global__ void __launch_bounds__(128*WN, WN == 1 ? 3 : 2) hmma2_k(
    const __nv_bfloat16* __restrict__ Ah, const __nv_bfloat16* __restrict__ Al, int lda, long sA,
    const __nv_bfloat16* __restrict__ Bh, const __nv_bfloat16* __restrict__ Bl, int ldb, long sB,
    float* __restrict__ C, int ldc, long sC,
    int K, float alpha,
    const float* __restrict__ bias, const float* __restrict__ resid,
    __nv_bfloat16* __restrict__ Ph, __nv_bfloat16* __restrict__ Pl, int ldp, long sP,
    __nv_bfloat16* __restrict__ Th, __nv_bfloat16* __restrict__ Tl, int ldt, long sT,
    int pAux, int tAux, float auxc,
    int splitK, long splitPitch)
{
    constexpr int BN = 64 * WN;
    constexpr int THREADS = 128 * WN;
    constexpr int B1 = BN * 80;
    constexpr int STG = 20480 + 2 * B1;
    extern __shared__ char dsm[];
    const uint32_t sb0 = smem_u32(dsm);

    const int tid = threadIdx.x;
    const int wid = tid >> 5, lid = tid & 31;
    const int wm = wid & 3, wn = wid >> 2;
    const int bz = blockIdx.z;
    const int b = bz / splitK, kseg = bz - b * splitK;
    const int Kseg = K / splitK;
    const int m0 = blockIdx.y * 128, n0 = blockIdx.x * BN;

    const __nv_bfloat16* pAh = Ah + (long)b * sA;
    const __nv_bfloat16* pAl = Al + (long)b * sA;
    const __nv_bfloat16* pBh = Bh + (long)b * sB;
    const __nv_bfloat16* pBl = Bl + (long)b * sB;

    float acc[2][8][4];
    #pragma unroll
    for (int i = 0; i < 2; i++)
        #pragma unroll
        for (int j = 0; j < 8; j++)
            #pragma unroll
            for (int q = 0; q < 4; q++) acc[i][j][q] = 0.f;

    auto load = [&](int kc, int st) {
        const uint32_t sb = sb0 + st * STG;
        #pragma unroll
        for (int it = 0; it < 512 / THREADS; it++) {
            int idx = it * THREADS + tid;
            int row = idx >> 2; int cb = (idx & 3) * 16; int ce = (idx & 3) * 8;
            uint32_t so = sb + row * 80 + cb;
            const long ga = (long)(m0 + row) * lda + kc + ce;
            cp16(so,         pAh + ga);
            cp16(so + 10240, pAl + ga);
        }
        #pragma unroll
        for (int it = 0; it < (BN * 4) / THREADS; it++) {
            int idx = it * THREADS + tid;
            int row = idx >> 2; int cb = (idx & 3) * 16; int ce = (idx & 3) * 8;
            uint32_t so = sb + 20480 + row * 80 + cb;
            const long gb = (long)(n0 + row) * ldb + kc + ce;
            cp16(so,      pBh + gb);
            cp16(so + B1, pBl + gb);
        }
    };

    const int k0 = kseg * Kseg;
    const int nch = Kseg / 32;
    load(k0, 0);
    CP_COMMIT();
    for (int c = 0; c < nch; c++) {
        if (c + 1 < nch) load(k0 + (c + 1) * 32, (c + 1) & 1);
        CP_COMMIT();
        CP_WAIT1();
        __syncthreads();
        const uint32_t uAh = sb0 + (c & 1) * STG;
        const uint32_t uAl = uAh + 10240;
        const uint32_t uBh = uAh + 20480;
        const uint32_t uBl = uBh + B1;
        #pragma unroll
        for (int ks = 0; ks < 2; ks++) {
            const int k16 = ks * 16;
            uint32_t ah[2][4], al[2][4];
            #pragma unroll
            for (int mt = 0; mt < 2; mt++) {
                int r = wm * 32 + mt * 16 + (lid & 15);
                int kk = k16 + ((lid >> 4) << 3);
                uint32_t off = (uint32_t)(r * 80 + kk * 2);
                ldsm4(ah[mt], uAh + off);
                ldsm4(al[mt], uAl + off);
            }
            #pragma unroll
            for (int p = 0; p < 4; p++) {
                int r = wn * 64 + p * 16 + ((lid >> 4) << 3) + (lid & 7);
                int kk = k16 + (lid & 8);
                uint32_t off = (uint32_t)(r * 80 + kk * 2);
                uint32_t bh[4], bl[4];
                ldsm4(bh, uBh + off);
                ldsm4(bl, uBl + off);
                #pragma unroll
                for (int mt = 0; mt < 2; mt++) {
                    #pragma unroll
                    for (int s = 0; s < 2; s++) {
                        float* cc = acc[mt][p * 2 + s];
                        mma16816(cc, ah[mt], &bh[2 * s]);
                        mma16816(cc, ah[mt], &bl[2 * s]);
                        mma16816(cc, al[mt], &bh[2 * s]);
                    }
                }
            }
        }
        __syncthreads();
    }

    float* Cb = C ? (splitK > 1 ? C + (long)bz * splitPitch : C + (long)b * sC) : nullptr;
    const int tr = lid >> 2, tc = (lid & 3) * 2;
    #pragma unroll
    for (int mt = 0; mt < 2; mt++)
        #pragma unroll
        for (int nt = 0; nt < 8; nt++) {
            int row = m0 + wm * 32 + mt * 16 + tr;
            int col = n0 + wn * 64 + nt * 8 + tc;
            float vv[2][2] = {{acc[mt][nt][0] * alpha, acc[mt][nt][1] * alpha},
                              {acc[mt][nt][2] * alpha, acc[mt][nt][3] * alpha}};
            if (bias) {
                float2 bb = *(const float2*)(bias + col);
                vv[0][0] += bb.x; vv[0][1] += bb.y; vv[1][0] += bb.x; vv[1][1] += bb.y;
            }
            #pragma unroll
            for (int rr = 0; rr < 2; rr++) {
                int ro = row + rr * 8;
                if (resid) {
                    float2 r2 = *(const float2*)(resid + (long)b * sC + (long)ro * ldc + col);
                    vv[rr][0] += r2.x; vv[rr][1] += r2.y;
                }
                if (Cb) *(float2*)(Cb + (long)ro * ldc + col) = make_float2(vv[rr][0], vv[rr][1]);
                if (Ph) {
                    float p0 = vv[rr][0], p1 = vv[rr][1];
                    if (pAux) {
                        p0 = (ro == col     ? auxc : 0.f) - p0;
                        p1 = (ro == col + 1 ? auxc : 0.f) - p1;
                    }
                    __nv_bfloat16 h0 = __float2bfloat16(p0);
                    __nv_bfloat16 h1 = __float2bfloat16(p1);
                    long off = (long)b * sP + (long)ro * ldp + col;
                    *(__nv_bfloat162*)(Ph + off) = __nv_bfloat162(h0, h1);
                    *(__nv_bfloat162*)(Pl + off) =
                        __nv_bfloat162(__float2bfloat16(p0 - __bfloat162float(h0)),
                                       __float2bfloat16(p1 - __bfloat162float(h1)));
                }
                if (Th) {
                    #pragma unroll
                    for (int cc = 0; cc < 2; cc++) {
                        float tv = vv[rr][cc];
                        if (tAux) tv = (ro == col + cc ? auxc : 0.f) - tv;
                        __nv_bfloat16 hh = __float2bfloat16(tv);
                        long off = (long)b * sT + (long)(col + cc) * ldt + ro;
                        Th[off] = hh;
                        Tl[off] = __float2bfloat16(tv - __bfloat162float(hh));
                    }
                }
            }
        }
}
static const int HS1 = 2 * (20480 + 2 * 64 * 80);    // 61440
static const int HS2 = 2 * (20480 + 2 * 128 * 80);   // 81920

// ---------------- bf16 split prep kernels ----------------
__global__ void split_k(const float* __restrict__ x, __nv_bfloat16* __restrict__ h,
                        __nv_bfloat16* __restrict__ l, int n4)
{
    int i = blockIdx.x * 256 + threadIdx.x;
    if (i >= n4) return;
    float4 v = ((const float4*)x)[i];
    __nv_bfloat16 h0 = __float2bfloat16(v.x), h1 = __float2bfloat16(v.y);
    __nv_bfloat16 h2 = __float2bfloat16(v.z), h3 = __float2bfloat16(v.w);
    __nv_bfloat162* hp = (__nv_bfloat162*)h;
    __nv_bfloat162* lp = (__nv_bfloat162*)l;
    hp[i*2]   = __nv_bfloat162(h0, h1);
    hp[i*2+1] = __nv_bfloat162(h2, h3);
    lp[i*2]   = __nv_bfloat162(__float2bfloat16(v.x - __bfloat162float(h0)),
                               __float2bfloat16(v.y - __bfloat162float(h1)));
    lp[i*2+1] = __nv_bfloat162(__float2bfloat16(v.z - __bfloat162float(h2)),
                               __float2bfloat16(v.w - __bfloat162float(h3)));
}
__global__ void splitT_k(const float* __restrict__ w, __nv_bfloat16* __restrict__ h,
                         __nv_bfloat16* __restrict__ l, int K, int N)
{
    int idx = blockIdx.x * 256 + threadIdx.x;
    if (idx >= N * K) return;
    int n = idx / K, k = idx - n * K;
    float v = w[(long)k * N + n];
    __nv_bfloat16 hb = __float2bfloat16(v);
    h[idx] = hb;
    l[idx] = __float2bfloat16(v - __bfloat162float(hb));
}
__global__ void vT_split_k(const float* __restrict__ qkv,
                           __nv_bfloat16* __restrict__ vh, __nv_bfloat16* __restrict__ vl)
{
    __shared__ float tile[64][65];
    int h = blockIdx.y, n0 = blockIdx.x * 64;
    int tid = threadIdx.x;
    for (int i = tid; i < 64 * 64; i += 256) {
        int r = i >> 6, c = i & 63;
        tile[r][c] = qkv[(long)(n0 + r) * (3*DM) + 2*DM + h * DH + c];
    }
    __syncthreads();
    for (int i = tid; i < 64 * 64; i += 256) {
        int c = i >> 6, r = i & 63;
        float v = tile[r][c];
        __nv_bfloat16 hb = __float2bfloat16(v);
        long off = ((long)h * DH + c) * NT + n0 + r;
        vh[off] = hb;
        vl[off] = __float2bfloat16(v - __bfloat162float(hb));
    }
}
// fused: reduce 16 split-K partials of t3 AND emit transposed bf16 hi/lo
__global__ void reduce_t3T(const float* __restrict__ part,
                           __nv_bfloat16* __restrict__ th, __nv_bfloat16* __restrict__ tl)
{
    int idx = blockIdx.x * 256 + threadIdx.x;
    if (idx >= NH * DH * LM) return;
    int h = idx >> 14, c = (idx >> 8) & 63, m = idx & 255;
    float s = 0.f;
    const float* p = part + ((long)h * 16 << 14) + (m << 6) + c;
    #pragma unroll
    for (int ss = 0; ss < 16; ss++) s += p[(long)ss << 14];
    __nv_bfloat16 hb = __float2bfloat16(s);
    th[idx] = hb;
    tl[idx] = __float2bfloat16(s - __bfloat162float(hb));
}
// z0 = a2^T * s
__global__ void pinv_init2(const float* __restrict__ a2, const float* __restrict__ sc,
                           __nv_bfloat16* __restrict__ zh, __nv_bfloat16* __restrict__ zl,
                           __nv_bfloat16* __restrict__ zth, __nv_bfloat16* __restrict__ ztl)
{
    int idx = blockIdx.x * 256 + threadIdx.x;
    int h = idx >> 16, r = (idx >> 8) & 255, c = idx & 255;
    float s = sc[0];
    float vt = a2[idx] * s;
    float vn = a2[(h << 16) + (c << 8) + r] * s;
    __nv_bfloat16 hn = __float2bfloat16(vn), ht = __float2bfloat16(vt);
    zh[idx] = hn; zl[idx] = __float2bfloat16(vn - __bfloat162float(hn));
    zth[idx] = ht; ztl[idx] = __float2bfloat16(vt - __bfloat162float(ht));
}

// ---------------- f32x2 helpers (SIMT gemm for attn2) ----------------
__device__ __forceinline__ unsigned long long dup2(float x) {
    unsigned long long r;
    asm("mov.b64 %0, {%1, %1};" : "=l"(r) : "f"(x));
    return r;
}
__device__ __forceinline__ void fma2(unsigned long long& d, unsigned long long a, unsigned long long b) {
    asm("fma.rn.f32x2 %0, %1, %2, %0;" : "+l"(d) : "l"(a), "l"(b));
}
__device__ __forceinline__ void unpack2(unsigned long long v, float& lo, float& hi) {
    asm("mov.b64 {%0, %1}, %2;" : "=f"(lo), "=f"(hi) : "l"(v));
}

// ---------------- reductions ----------------
__device__ __forceinline__ float warpSum(float v) {
    #pragma unroll
    for (int o = 16; o; o >>= 1) v += __shfl_xor_sync(0xffffffffu, v, o);
    return v;
}
__device__ __forceinline__ float warpMax(float v) {
    #pragma unroll
    for (int o = 16; o; o >>= 1) v = fmaxf(v, __shfl_xor_sync(0xffffffffu, v, o));
    return v;
}
__device__ float blockSum(float v) {
    __shared__ float sh[33];
    int lane = threadIdx.x & 31, wid = threadIdx.x >> 5;
    v = warpSum(v);
    __syncthreads();
    if (lane == 0) sh[wid] = v;
    __syncthreads();
    int nw = blockDim.x >> 5;
    float r = (wid == 0 && lane < nw) ? sh[lane] : 0.f;
    if (wid == 0) { r = warpSum(r); if (lane == 0) sh[32] = r; }
    __syncthreads();
    return sh[32];
}
__device__ float blockMax(float v) {
    __shared__ float sh[33];
    int lane = threadIdx.x & 31, wid = threadIdx.x >> 5;
    v = warpMax(v);
    __syncthreads();
    if (lane == 0) sh[wid] = v;
    __syncthreads();
    int nw = blockDim.x >> 5;
    float r = (wid == 0 && lane < nw) ? sh[lane] : -FLT_MAX;
    if (wid == 0) { r = warpMax(r); if (lane == 0) sh[32] = r; }
    __syncthreads();
    return sh[32];
}

// ---------------- SIMT GEMM (attn2 only) ----------------
template<int BM, int BN, int BK, int TM, int TN, bool TB>
__global__ __launch_bounds__((BM/TM)*(BN/TN))
void gemm_k(const float* __restrict__ A, int lda, long sA,
            const float* __restrict__ B, int ldb, long sB,
            float* __restrict__ C, int ldc, long sC,
            int K, float alpha)
{
    constexpr int THREADS = (BM/TM)*(BN/TN);
    __shared__ __align__(16) float As[BM][BK + 4];
    __shared__ __align__(16) float Bs[BK][BN + 4];
    const int tid = threadIdx.x;
    const int batch = blockIdx.z;
    const int m0 = blockIdx.y * BM, n0 = blockIdx.x * BN;
    const float* Ab = A + (long)batch * sA + (long)m0 * lda;
    const float* Bb = B + (long)batch * sB;

    unsigned long long acc[TM][TN/2];
    #pragma unroll
    for (int i = 0; i < TM; i++)
        #pragma unroll
        for (int j = 0; j < TN/2; j++) acc[i][j] = 0ull;

    const int tx = tid % (BN/TN), ty = tid / (BN/TN);

    for (int k0 = 0; k0 < K; k0 += BK) {
        #pragma unroll
        for (int idx = tid; idx < BM*(BK/4); idx += THREADS) {
            int m = idx / (BK/4), kq = idx - m * (BK/4);
            float4 v = *(const float4*)(Ab + (long)m * lda + k0 + kq*4);
            *(float4*)&As[m][kq*4] = v;
        }
        if (!TB) {
            #pragma unroll
            for (int idx = tid; idx < BK*(BN/4); idx += THREADS) {
                int kk = idx / (BN/4), nq = idx - kk * (BN/4);
                float4 v = *(const float4*)(Bb + (long)(k0+kk) * ldb + n0 + nq*4);
                *(float4*)&Bs[kk][nq*4] = v;
            }
        } else {
            #pragma unroll
            for (int idx = tid; idx < BN*(BK/4); idx += THREADS) {
                int n = idx / (BK/4), kq = idx - n * (BK/4);
                float4 v = *(const float4*)(Bb + (long)(n0+n) * ldb + k0 + kq*4);
                Bs[kq*4+0][n] = v.x; Bs[kq*4+1][n] = v.y;
                Bs[kq*4+2][n] = v.z; Bs[kq*4+3][n] = v.w;
            }
        }
        __syncthreads();
        #pragma unroll
        for (int kk = 0; kk < BK; kk++) {
            unsigned long long bb[TN/2];
            #pragma unroll
            for (int q = 0; q < TN/4; q++) {
                ulonglong2 bv = *(const ulonglong2*)&Bs[kk][tx*TN + q*4];
                bb[q*2]   = bv.x;
                bb[q*2+1] = bv.y;
            }
            #pragma unroll
            for (int i = 0; i < TM; i++) {
                unsigned long long aa = dup2(As[ty*TM + i][kk]);
                #pragma unroll
                for (int j = 0; j < TN/2; j++) fma2(acc[i][j], aa, bb[j]);
            }
        }
        __syncthreads();
    }

    float* Cb = C + (long)batch * sC;
    #pragma unroll
    for (int i = 0; i < TM; i++) {
        int m = m0 + ty*TM + i;
        #pragma unroll
        for (int j = 0; j < TN/2; j++) {
            float lo, hi;
            unpack2(acc[i][j], lo, hi);
            Cb[(long)m * ldc + n0 + tx*TN + 2*j]     = alpha * lo;
            Cb[(long)m * ldc + n0 + tx*TN + 2*j + 1] = alpha * hi;
        }
    }
}

// ---------------- landmarks ----------------
__global__ void landmarks_k(const float* __restrict__ qkv, float* __restrict__ ql, float* __restrict__ kl,
                            __nv_bfloat16* __restrict__ qlh, __nv_bfloat16* __restrict__ qll,
                            __nv_bfloat16* __restrict__ klh, __nv_bfloat16* __restrict__ kll)
{
    int hm = blockIdx.x;
    int h = hm >> 8, mm = hm & 255;
    int d = threadIdx.x;
    const float* base = qkv + (long)(mm * 32) * (3*DM) + h * DH + d;
    float sq = 0.f, sk = 0.f;
    #pragma unroll 8
    for (int r = 0; r < 32; r++) { sq += base[r * (3*DM)]; sk += base[r * (3*DM) + DM]; }
    float q = sq * (1.f / 32.f) * 0.125f;
    float k = sk * (1.f / 32.f);
    int o = hm * DH + d;
    ql[o] = q; kl[o] = k;
    __nv_bfloat16 qh = __float2bfloat16(q), kh = __float2bfloat16(k);
    qlh[o] = qh; qll[o] = __float2bfloat16(q - __bfloat162float(qh));
    klh[o] = kh; kll[o] = __float2bfloat16(k - __bfloat162float(kh));
}

// ---------------- softmaxes ----------------
__device__ __forceinline__ void store_split4(__nv_bfloat16* ph, __nv_bfloat16* pl, float4 v)
{
    __nv_bfloat16 h0 = __float2bfloat16(v.x), h1 = __float2bfloat16(v.y);
    __nv_bfloat16 h2 = __float2bfloat16(v.z), h3 = __float2bfloat16(v.w);
    *(__nv_bfloat162*)ph = __nv_bfloat162(h0, h1);
    *(__nv_bfloat162*)(ph+2) = __nv_bfloat162(h2, h3);
    *(__nv_bfloat162*)pl = __nv_bfloat162(__float2bfloat16(v.x - __bfloat162float(h0)),
                                          __float2bfloat16(v.y - __bfloat162float(h1)));
    *(__nv_bfloat162*)(pl+2) = __nv_bfloat162(__float2bfloat16(v.z - __bfloat162float(h2)),
                                              __float2bfloat16(v.w - __bfloat162float(h3)));
}

__global__ void softmax256(float* __restrict__ d, __nv_bfloat16* __restrict__ oh, __nv_bfloat16* __restrict__ ol)
{
    int warp = threadIdx.x >> 5, lane = threadIdx.x & 31;
    long row = (long)blockIdx.x * 8 + warp;
    float* p = d + row * 256;
    float4 v0 = *(float4*)(p + lane*4);
    float4 v1 = *(float4*)(p + 128 + lane*4);
    float mx = fmaxf(fmaxf(fmaxf(v0.x, v0.y), fmaxf(v0.z, v0.w)),
                     fmaxf(fmaxf(v1.x, v1.y), fmaxf(v1.z, v1.w)));
    mx = warpMax(mx);
    v0.x = __expf(v0.x - mx); v0.y = __expf(v0.y - mx);
    v0.z = __expf(v0.z - mx); v0.w = __expf(v0.w - mx);
    v1.x = __expf(v1.x - mx); v1.y = __expf(v1.y - mx);
    v1.z = __expf(v1.z - mx); v1.w = __expf(v1.w - mx);
    float s = v0.x + v0.y + v0.z + v0.w + v1.x + v1.y + v1.z + v1.w;
    s = warpSum(s);
    float inv = 1.f / s;
    v0.x *= inv; v0.y *= inv; v0.z *= inv; v0.w *= inv;
    v1.x *= inv; v1.y *= inv; v1.z *= inv; v1.w *= inv;
    if (oh) {
        store_split4(oh + row*256 + lane*4, ol + row*256 + lane*4, v0);
        store_split4(oh + row*256 + 128 + lane*4, ol + row*256 + 128 + lane*4, v1);
    } else {
        *(float4*)(p + lane*4) = v0;
        *(float4*)(p + 128 + lane*4) = v1;
    }
}

__global__ __launch_bounds__(256)
void softmax8192(float* __restrict__ d, __nv_bfloat16* __restrict__ oh, __nv_bfloat16* __restrict__ ol)
{
    long rb = (long)blockIdx.x * 8192;
    float* p = d + rb;
    int t = threadIdx.x;
    float4 v[8];
    float mx = -FLT_MAX;
    #pragma unroll
    for (int q = 0; q < 8; q++) {
        v[q] = *(float4*)(p + (q*256 + t)*4);
        mx = fmaxf(mx, fmaxf(fmaxf(v[q].x, v[q].y), fmaxf(v[q].z, v[q].w)));
    }
    mx = blockMax(mx);
    float s = 0.f;
    #pragma unroll
    for (int q = 0; q < 8; q++) {
        v[q].x = __expf(v[q].x - mx); v[q].y = __expf(v[q].y - mx);
        v[q].z = __expf(v[q].z - mx); v[q].w = __expf(v[q].w - mx);
        s += v[q].x + v[q].y + v[q].z + v[q].w;
    }
    s = blockSum(s);
    float inv = 1.f / s;
    #pragma unroll
    for (int q = 0; q < 8; q++) {
        v[q].x *= inv; v[q].y *= inv; v[q].z *= inv; v[q].w *= inv;
        store_split4(oh + rb + (q*256 + t)*4, ol + rb + (q*256 + t)*4, v[q]);
    }
}

// ---------------- pinv scale helpers ----------------
__global__ void absmax_sums(const float* __restrict__ x, float* __restrict__ rs, float* __restrict__ cs)
{
    int h = blockIdx.x, t = threadIdx.x;
    const float* base = x + (long)h * LM * LM;
    float r = 0.f;
    const float* rp = base + (long)t * LM;
    #pragma unroll 8
    for (int i = 0; i < LM; i++) r += fabsf(rp[i]);
    rs[h * LM + t] = r;
    float c = 0.f;
    const float* cp = base + t;
    #pragma unroll 8
    for (int i = 0; i < LM; i++) c += fabsf(cp[i * LM]);
    cs[h * LM + t] = c;
}
__global__ void calc_scale(const float* __restrict__ rs, const float* __restrict__ cs, float* __restrict__ sc)
{
    float mr = -FLT_MAX, mc = -FLT_MAX;
    for (int i = threadIdx.x; i < NH * LM; i += blockDim.x) {
        mr = fmaxf(mr, rs[i]); mc = fmaxf(mc, cs[i]);
    }
    mr = blockMax(mr); mc = blockMax(mc);
    if (threadIdx.x == 0) sc[0] = 1.f / (mr * mc);
}

// ---------------- depthwise conv (standalone result buffer) ----------------
__global__ void conv_store_k(const float* __restrict__ qkv, const float* __restrict__ cw,
                             float* __restrict__ convres)
{
    __shared__ float ws[NH * CK];
    for (int t = threadIdx.x; t < NH * CK; t += blockDim.x) ws[t] = cw[t];
    __syncthreads();
    int idx = blockIdx.x * blockDim.x + threadIdx.x;
    if (idx >= NT * DM) return;
    int c = idx & (DM - 1);
    int n = idx >> 9;
    int h = c >> 6;
    const float* wrow = ws + h * CK;
    float acc = 0.f;
    #pragma unroll
    for (int k = 0; k < CK; k++) {
        int nn = n - (CK/2) + k;
        if (nn >= 0 && nn < NT) acc += wrow[k] * qkv[(long)nn * (3*DM) + 2*DM + c];
    }
    convres[idx] = acc;
}

// ---------------- A_raw ----------------
__global__ void araw_k(const float* __restrict__ adj, const float* __restrict__ q2,
                       const float* __restrict__ k2, float* __restrict__ Araw)
{
    int i = blockIdx.x;
    __shared__ float qs[ATTD];
    qs[threadIdx.x] = q2[(long)i * ATTD + threadIdx.x];
    __syncthreads();
    float acc = 0.f;
    const float4* arow = (const float4*)(adj + (long)i * NT);
    const float4* q4 = (const float4*)qs;
    for (int t = threadIdx.x; t < NT/4; t += blockDim.x) {
        float4 a4 = arow[t];
        float av[4] = {a4.x, a4.y, a4.z, a4.w};
        #pragma unroll
        for (int c = 0; c < 4; c++) {
            if (av[c] != 0.f) {
                int j = t * 4 + c;
                const float4* k4 = (const float4*)(k2 + (long)j * ATTD);
                float dot = 0.f;
                #pragma unroll 8
                for (int d = 0; d < ATTD/4; d++) {
                    float4 a = q4[d], b = k4[d];
                    dot += a.x*b.x + a.y*b.y + a.z*b.z + a.w*b.w;
                }
                acc += av[c] * dot;
            }
        }
    }
    acc = blockSum(acc);
    if (threadIdx.x == 0) Araw[i] = acc * (1.f / 16.f);
}

__global__ void alpha_softmax_k(const float* __restrict__ Araw, float* __restrict__ alpha)
{
    float mx = -FLT_MAX;
    for (int i = threadIdx.x; i < NT; i += blockDim.x) mx = fmaxf(mx, Araw[i]);
    mx = blockMax(mx);
    float s = 0.f;
    for (int i = threadIdx.x; i < NT; i += blockDim.x) {
        float e = __expf(Araw[i] - mx); alpha[i] = e; s += e;
    }
    s = blockSum(s);
    float inv = 1.f / s;
    for (int i = threadIdx.x; i < NT; i += blockDim.x) alpha[i] *= inv;
}

// ---------------- final elementwise ----------------
__global__ void final_k(const float* __restrict__ val, const float* __restrict__ enc,
                        const float* __restrict__ alpha, const float* __restrict__ Araw,
                        float* __restrict__ out)
{
    int idx = blockIdx.x * blockDim.x + threadIdx.x;
    if (idx >= NT * DM) return;
    int n = idx >> 9;
    float xl = alpha[n] * val[idx];
    float wei = 1.f / (1.f + __expf(xl));
    float sq = wei * wei;
    out[idx] = xl * 2.f * sq + 2.f * enc[idx] * (1.f - sq);
    if (idx < NT) out[(long)NT * DM + idx] = Araw[idx];
}

// ---------------- host ----------------
#define GEMM_MED_T gemm_k<64,64,16,4,4,true>
#define NB16 (__nv_bfloat16*)nullptr
#define F32N (float*)nullptr

// Streams/events created exactly once on first call (correctness run, before the
// harness's pre-capture memory baseline); reused every call thereafter.
struct SideCtx {
    cudaStream_t s1, s2;
    cudaEvent_t evStart, ev0, evW, evQkv, evLm, evZ, evVal, evConv, evVT, evEnc, evK2;
    SideCtx() {
        cudaStreamCreateWithFlags(&s1, cudaStreamNonBlocking);
        cudaStreamCreateWithFlags(&s2, cudaStreamNonBlocking);
        cudaEventCreateWithFlags(&evStart, cudaEventDisableTiming);
        cudaEventCreateWithFlags(&ev0, cudaEventDisableTiming);
        cudaEventCreateWithFlags(&evW, cudaEventDisableTiming);
        cudaEventCreateWithFlags(&evQkv, cudaEventDisableTiming);
        cudaEventCreateWithFlags(&evLm, cudaEventDisableTiming);
        cudaEventCreateWithFlags(&evZ, cudaEventDisableTiming);
        cudaEventCreateWithFlags(&evVal, cudaEventDisableTiming);
        cudaEventCreateWithFlags(&evConv, cudaEventDisableTiming);
        cudaEventCreateWithFlags(&evVT, cudaEventDisableTiming);
        cudaEventCreateWithFlags(&evEnc, cudaEventDisableTiming);
        cudaEventCreateWithFlags(&evK2, cudaEventDisableTiming);
    }
};

extern "C" void kernel_launch(void* const* d_in, const int* in_sizes, int n_in,
                              void* d_out, int out_size)
{
    static SideCtx ctx;
    cudaStream_t s1 = ctx.s1, s2 = ctx.s2;

    const float* dense = (const float*)d_in[0];
    const float* adj   = (const float*)d_in[1];
    const float* wq    = (const float*)d_in[2];
    const float* wk    = (const float*)d_in[3];
    const float* wv_w  = (const float*)d_in[4];
    const float* wv_b  = (const float*)d_in[5];
    const float* qkv_w = (const float*)d_in[6];
    const float* out_w = (const float*)d_in[7];
    const float* out_b = (const float*)d_in[8];
    const float* conv_w= (const float*)d_in[9];
    float* out = (float*)d_out;

    float *qkv, *ql, *kl, *a1, *a3, *a2, *t3p, *convres, *enc, *q2, *k2, *val;
    float *Araw, *alpha, *rs, *cs, *sc;
    __nv_bfloat16 *dh, *dl, *th, *tl, *ench, *encl, *wth, *wtl, *wvth, *wvtl;
    __nv_bfloat16 *woth, *wotl, *wqth, *wqtl, *wkth, *wktl, *qkvh, *qkvl;
    __nv_bfloat16 *a1h, *a1l, *a3h, *a3l, *vth, *vtl, *qlh, *qll, *klh, *kll;
    __nv_bfloat16 *t3th, *t3tl, *t4th, *t4tl;
    __nv_bfloat16 *a2h, *a2l, *zAh, *zAl, *zATh, *zATl, *zBh, *zBl, *zBTh, *zBTl;
    __nv_bfloat16 *xzh, *xzl, *t1Th, *t1Tl, *uTh, *uTl, *wTh, *wTl;
    cudaGetSymbolAddress((void**)&qkv, g_qkv);
    cudaGetSymbolAddress((void**)&ql, g_ql);
    cudaGetSymbolAddress((void**)&kl, g_kl);
    cudaGetSymbolAddress((void**)&a1, g_attn1);
    cudaGetSymbolAddress((void**)&a3, g_attn3);
    cudaGetSymbolAddress((void**)&a2, g_attn2);
    cudaGetSymbolAddress((void**)&t3p, g_t3p);
    cudaGetSymbolAddress((void**)&convres, g_convres);
    cudaGetSymbolAddress((void**)&enc, g_enc);
    cudaGetSymbolAddress((void**)&q2, g_q2);
    cudaGetSymbolAddress((void**)&k2, g_k2);
    cudaGetSymbolAddress((void**)&val, g_val);
    cudaGetSymbolAddress((void**)&Araw, g_Araw);
    cudaGetSymbolAddress((void**)&alpha, g_alpha);
    cudaGetSymbolAddress((void**)&rs, g_rs);
    cudaGetSymbolAddress((void**)&cs, g_cs);
    cudaGetSymbolAddress((void**)&sc, g_scale);
    cudaGetSymbolAddress((void**)&dh, g_dh);
    cudaGetSymbolAddress((void**)&dl, g_dl);
    cudaGetSymbolAddress((void**)&th, g_th);
    cudaGetSymbolAddress((void**)&tl, g_tl);
    cudaGetSymbolAddress((void**)&ench, g_ench);
    cudaGetSymbolAddress((void**)&encl, g_encl);
    cudaGetSymbolAddress((void**)&wth, g_wth);
    cudaGetSymbolAddress((void**)&wtl, g_wtl);
    cudaGetSymbolAddress((void**)&wvth, g_wvth);
    cudaGetSymbolAddress((void**)&wvtl, g_wvtl);
    cudaGetSymbolAddress((void**)&woth, g_woth);
    cudaGetSymbolAddress((void**)&wotl, g_wotl);
    cudaGetSymbolAddress((void**)&wqth, g_wqth);
    cudaGetSymbolAddress((void**)&wqtl, g_wqtl);
    cudaGetSymbolAddress((void**)&wkth, g_wkth);
    cudaGetSymbolAddress((void**)&wktl, g_wktl);
    cudaGetSymbolAddress((void**)&qkvh, g_qkvh);
    cudaGetSymbolAddress((void**)&qkvl, g_qkvl);
    cudaGetSymbolAddress((void**)&a1h, g_a1h);
    cudaGetSymbolAddress((void**)&a1l, g_a1l);
    cudaGetSymbolAddress((void**)&a3h, g_a3h);
    cudaGetSymbolAddress((void**)&a3l, g_a3l);
    cudaGetSymbolAddress((void**)&vth, g_vth);
    cudaGetSymbolAddress((void**)&vtl, g_vtl);
    cudaGetSymbolAddress((void**)&qlh, g_qlh);
    cudaGetSymbolAddress((void**)&qll, g_qll);
    cudaGetSymbolAddress((void**)&klh, g_klh);
    cudaGetSymbolAddress((void**)&kll, g_kll);
    cudaGetSymbolAddress((void**)&t3th, g_t3th);
    cudaGetSymbolAddress((void**)&t3tl, g_t3tl);
    cudaGetSymbolAddress((void**)&t4th, g_t4th);
    cudaGetSymbolAddress((void**)&t4tl, g_t4tl);
    cudaGetSymbolAddress((void**)&a2h, g_a2h);
    cudaGetSymbolAddress((void**)&a2l, g_a2l);
    cudaGetSymbolAddress((void**)&zAh, g_zAh);
    cudaGetSymbolAddress((void**)&zAl, g_zAl);
    cudaGetSymbolAddress((void**)&zATh, g_zATh);
    cudaGetSymbolAddress((void**)&zATl, g_zATl);
    cudaGetSymbolAddress((void**)&zBh, g_zBh);
    cudaGetSymbolAddress((void**)&zBl, g_zBl);
    cudaGetSymbolAddress((void**)&zBTh, g_zBTh);
    cudaGetSymbolAddress((void**)&zBTl, g_zBTl);
    cudaGetSymbolAddress((void**)&xzh, g_xzh);
    cudaGetSymbolAddress((void**)&xzl, g_xzl);
    cudaGetSymbolAddress((void**)&t1Th, g_t1Th);
    cudaGetSymbolAddress((void**)&t1Tl, g_t1Tl);
    cudaGetSymbolAddress((void**)&uTh, g_uTh);
    cudaGetSymbolAddress((void**)&uTl, g_uTl);
    cudaGetSymbolAddress((void**)&wTh, g_wTh);
    cudaGetSymbolAddress((void**)&wTl, g_wTl);

    cudaFuncSetAttribute(hmma2_k<1>, cudaFuncAttributeMaxDynamicSharedMemorySize, HS1);
    cudaFuncSetAttribute(hmma2_k<2>, cudaFuncAttributeMaxDynamicSharedMemorySize, HS2);

    const long HL = (long)LM * LM;

    // fork point: both side streams join the capture graph via this event
    cudaEventRecord(ctx.evStart, 0);
    cudaStreamWaitEvent(s1, ctx.evStart, 0);
    cudaStreamWaitEvent(s2, ctx.evStart, 0);

    // --- s1 head: input-only weight splits (out_w, wq, wk) ---
    splitT_k<<<(DM*DM + 255)/256, 256, 0, s1>>>(out_w, woth, wotl, DM, DM);
    splitT_k<<<(DM*ATTD + 255)/256, 256, 0, s1>>>(wq, wqth, wqtl, DM, ATTD);
    splitT_k<<<(DM*ATTD + 255)/256, 256, 0, s1>>>(wk, wkth, wktl, DM, ATTD);
    cudaEventRecord(ctx.evW, s1);

    // --- s2 head: wv split (input-only) ---
    splitT_k<<<(DM*DM + 255)/256, 256, 0, s2>>>(wv_w, wvth, wvtl, DM, DM);

    // 1. split dense (main); s2 then runs val GEMM
    split_k<<<(NT*DM/4 + 255)/256, 256>>>(dense, dh, dl, NT*DM/4);
    cudaEventRecord(ctx.ev0, 0);
    cudaStreamWaitEvent(s2, ctx.ev0, 0);
    hmma2_k<2><<<dim3(4, 64, 1), 256, HS2, s2>>>(dh, dl, DM, 0, wvth, wvtl, DM, 0,
        val, DM, 0, DM, 1.f, wv_b, nullptr, NB16, NB16, 0, 0, NB16, NB16, 0, 0, 0, 0, 0.f, 1, 0);
    cudaEventRecord(ctx.evVal, s2);

    // main: qkv = dense @ qkv_w
    splitT_k<<<(3*DM*DM + 255)/256, 256>>>(qkv_w, wth, wtl, DM, 3*DM);
    hmma2_k<2><<<dim3(12, 64, 1), 256, HS2>>>(dh, dl, DM, 0, wth, wtl, DM, 0,
        qkv, 3*DM, 0, DM, 1.f, nullptr, nullptr,
        qkvh, qkvl, 3*DM, 0, NB16, NB16, 0, 0, 0, 0, 0.f, 1, 0);
    cudaEventRecord(ctx.evQkv, 0);

    // s2 (after qkv): vT split + depthwise conv into convres
    cudaStreamWaitEvent(s2, ctx.evQkv, 0);
    vT_split_k<<<dim3(NT/64, NH), 256, 0, s2>>>(qkv, vth, vtl);
    cudaEventRecord(ctx.evVT, s2);
    conv_store_k<<<(NT*DM + 255)/256, 256, 0, s2>>>(qkv, conv_w, convres);
    cudaEventRecord(ctx.evConv, s2);

    // 2. landmarks; fork s1 for the pinv chain
    landmarks_k<<<NH*LM, DH>>>(qkv, ql, kl, qlh, qll, klh, kll);
    cudaEventRecord(ctx.evLm, 0);
    cudaStreamWaitEvent(s1, ctx.evLm, 0);

    // --- s1: attn2 + pinv Newton-Schulz ---
    GEMM_MED_T<<<dim3(LM/64, LM/64, NH), 256, 0, s1>>>(
        ql, DH, (long)LM*DH, kl, DH, (long)LM*DH, a2, LM, HL, DH, 1.f);
    softmax256<<<NH*LM/8, 256, 0, s1>>>(a2, nullptr, nullptr);
    absmax_sums<<<NH, 256, 0, s1>>>(a2, rs, cs);
    calc_scale<<<1, 256, 0, s1>>>(rs, cs, sc);
    split_k<<<NH*LM*LM/4/256, 256, 0, s1>>>(a2, a2h, a2l, NH*LM*LM/4);
    pinv_init2<<<NH*LM*LM/256, 256, 0, s1>>>(a2, sc, zAh, zAl, zATh, zATl);

    __nv_bfloat16 *zinh = zAh, *zinl = zAl, *zinTh = zATh, *zinTl = zATl;
    __nv_bfloat16 *zoth = zBh, *zotl = zBl, *zotTh = zBTh, *zotTl = zBTl;
    const dim3 pgrid(4, 2, NH);
    for (int it = 0; it < 6; it++) {
        hmma2_k<1><<<pgrid, 128, HS1, s1>>>(a2h, a2l, LM, HL, zinTh, zinTl, LM, HL,
            F32N, 0, 0, LM, 1.f, nullptr, nullptr,
            xzh, xzl, LM, HL, t1Th, t1Tl, LM, HL, 0, 1, 7.f, 1, 0);
        hmma2_k<1><<<pgrid, 128, HS1, s1>>>(xzh, xzl, LM, HL, t1Th, t1Tl, LM, HL,
            F32N, 0, 0, LM, 1.f, nullptr, nullptr,
            NB16, NB16, 0, 0, uTh, uTl, LM, HL, 0, 1, 15.f, 1, 0);
        hmma2_k<1><<<pgrid, 128, HS1, s1>>>(xzh, xzl, LM, HL, uTh, uTl, LM, HL,
            F32N, 0, 0, LM, 1.f, nullptr, nullptr,
            NB16, NB16, 0, 0, wTh, wTl, LM, HL, 0, 1, 13.f, 1, 0);
        hmma2_k<1><<<pgrid, 128, HS1, s1>>>(zinh, zinl, LM, HL, wTh, wTl, LM, HL,
            F32N, 0, 0, LM, 0.25f, nullptr, nullptr,
            zoth, zotl, LM, HL, zotTh, zotTl, LM, HL, 0, 0, 0.f, 1, 0);
        __nv_bfloat16* t;
        t = zinh; zinh = zoth; zoth = t;   t = zinl; zinl = zotl; zotl = t;
        t = zinTh; zinTh = zotTh; zotTh = t; t = zinTl; zinTl = zotTl; zotTl = t;
    }
    cudaEventRecord(ctx.evZ, s1);

    // --- main stream: attention chain ---
    // 3. attn1 logits
    hmma2_k<2><<<dim3(2, 64, NH), 256, HS2>>>(qkvh, qkvl, 3*DM, DH, klh, kll, DH, (long)LM*DH,
        a1, LM, (long)NT*LM, DH, 0.125f, nullptr, nullptr,
        NB16, NB16, 0, 0, NB16, NB16, 0, 0, 0, 0, 0.f, 1, 0);
    softmax256<<<NH*NT/8, 256>>>(a1, a1h, a1l);

    // 5. attn3 logits
    hmma2_k<2><<<dim3(64, 2, NH), 256, HS2>>>(qlh, qll, DH, (long)LM*DH, qkvh + DM, qkvl + DM, 3*DM, DH,
        a3, NT, (long)LM*NT, DH, 1.f, nullptr, nullptr,
        NB16, NB16, 0, 0, NB16, NB16, 0, 0, 0, 0, 0.f, 1, 0);
    softmax8192<<<NH*LM, 256>>>(a3, a3h, a3l);

    // 8. t3 = attn3 @ v  (split-K=16); vT from s2
    cudaStreamWaitEvent(0, ctx.evVT, 0);
    hmma2_k<1><<<dim3(1, 2, NH*16), 128, HS1>>>(a3h, a3l, NT, (long)LM*NT, vth, vtl, NT, (long)DH*NT,
        t3p, DH, 0, NT, 1.f, nullptr, nullptr,
        NB16, NB16, 0, 0, NB16, NB16, 0, 0, 0, 0, 0.f, 16, (long)LM*DH);
    reduce_t3T<<<(NH*DH*LM + 255)/256, 256>>>(t3p, t3th, t3tl);

    // join pinv
    cudaStreamWaitEvent(0, ctx.evZ, 0);

    // 9. t4 = pinv @ t3
    hmma2_k<1><<<dim3(1, 2, NH), 128, HS1>>>(zinh, zinl, LM, HL, t3th, t3tl, LM, (long)DH*LM,
        F32N, 0, 0, LM, 1.f, nullptr, nullptr,
        NB16, NB16, 0, 0, t4th, t4tl, LM, (long)DH*LM, 0, 0, 0.f, 1, 0);

    // 10. outh = attn1 @ t4 + convres; emits bf16 hi/lo directly to th/tl (no fp32 C)
    cudaStreamWaitEvent(0, ctx.evConv, 0);
    hmma2_k<1><<<dim3(1, 64, NH), 128, HS1>>>(a1h, a1l, LM, (long)NT*LM, t4th, t4tl, LM, (long)DH*LM,
        F32N, DM, DH, LM, 1.f, nullptr, convres,
        th, tl, DM, DH, NB16, NB16, 0, 0, 0, 0, 0.f, 1, 0);

    // 12. enc = outh @ out_w + out_b + dense ; emits bf16 hi/lo to ench/encl
    cudaStreamWaitEvent(0, ctx.evW, 0);
    hmma2_k<2><<<dim3(4, 64, 1), 256, HS2>>>(th, tl, DM, 0, woth, wotl, DM, 0,
        enc, DM, 0, DM, 1.f, out_b, dense, ench, encl, DM, 0, NB16, NB16, 0, 0, 0, 0, 0.f, 1, 0);
    cudaEventRecord(ctx.evEnc, 0);

    // 13. q2 (main) ; k2 (s2, concurrent). enc bf16 in ench/encl.
    cudaStreamWaitEvent(s2, ctx.evEnc, 0);
    hmma2_k<2><<<dim3(2, 64, 1), 256, HS2, s2>>>(ench, encl, DM, 0, wkth, wktl, DM, 0,
        k2, ATTD, 0, DM, 1.f, nullptr, nullptr, NB16, NB16, 0, 0, NB16, NB16, 0, 0, 0, 0, 0.f, 1, 0);
    cudaEventRecord(ctx.evK2, s2);
    hmma2_k<2><<<dim3(2, 64, 1), 256, HS2>>>(ench, encl, DM, 0, wqth, wqtl, DM, 0,
        q2, ATTD, 0, DM, 1.f, nullptr, nullptr, NB16, NB16, 0, 0, NB16, NB16, 0, 0, 0, 0, 0.f, 1, 0);

    // 15. A_raw
    cudaStreamWaitEvent(0, ctx.evK2, 0);
    araw_k<<<NT, 256>>>(adj, q2, k2, Araw);

    // 16. alpha = softmax(A_raw)
    alpha_softmax_k<<<1, 1024>>>(Araw, alpha);

    // 17. final
    cudaStreamWaitEvent(0, ctx.evVal, 0);
    final_k<<<(NT*DM + 255)/256, 256>>>(val, enc, alpha, Araw, out);
}

// round 17
// speedup vs baseline: 1.0245x; 1.0067x over previous
#include <cuda_runtime.h>
#include <cuda_bf16.h>
#include <float.h>
#include <stdint.h>

#define NT   8192
#define DM   512
#define NH   8
#define DH   64
#define LM   256
#define ATTD 256
#define CK   33

// ---------------- device scratch ----------------
__device__ float g_qkv[NT * 3 * DM];
__device__ float g_ql[NH * LM * DH];
__device__ float g_kl[NH * LM * DH];
__device__ float g_attn3[(size_t)NH * LM * NT];
__device__ float g_attn2[NH * LM * LM];
__device__ float g_t3p[16 * NH * LM * DH];
__device__ float g_convres[NT * DM];
__device__ float g_enc [NT * DM];
__device__ float g_q2[NT * ATTD];
__device__ float g_k2[NT * ATTD];
__device__ float g_val[NT * DM];
__device__ float g_Araw[NT];
__device__ float g_alpha[NT];
__device__ float g_rs[NH * LM];
__device__ float g_cs[NH * LM];
__device__ float g_scale[1];
// bf16 buffers
__device__ __nv_bfloat16 g_dh[NT * DM];
__device__ __nv_bfloat16 g_dl[NT * DM];
__device__ __nv_bfloat16 g_th[NT * DM];
__device__ __nv_bfloat16 g_tl[NT * DM];
__device__ __nv_bfloat16 g_ench[NT * DM];
__device__ __nv_bfloat16 g_encl[NT * DM];
__device__ __nv_bfloat16 g_wth[3 * DM * DM];   // qkv_w split
__device__ __nv_bfloat16 g_wtl[3 * DM * DM];
__device__ __nv_bfloat16 g_wvth[DM * DM];
__device__ __nv_bfloat16 g_wvtl[DM * DM];
__device__ __nv_bfloat16 g_woth[DM * DM];      // out_w split
__device__ __nv_bfloat16 g_wotl[DM * DM];
__device__ __nv_bfloat16 g_wqth[DM * ATTD];
__device__ __nv_bfloat16 g_wqtl[DM * ATTD];
__device__ __nv_bfloat16 g_wkth[DM * ATTD];
__device__ __nv_bfloat16 g_wktl[DM * ATTD];
__device__ __nv_bfloat16 g_qkvh[NT * 3 * DM];
__device__ __nv_bfloat16 g_qkvl[NT * 3 * DM];
__device__ __nv_bfloat16 g_a1h[(size_t)NH * NT * LM];
__device__ __nv_bfloat16 g_a1l[(size_t)NH * NT * LM];
__device__ __nv_bfloat16 g_a3h[(size_t)NH * LM * NT];
__device__ __nv_bfloat16 g_a3l[(size_t)NH * LM * NT];
__device__ __nv_bfloat16 g_vth[NH * DH * NT];
__device__ __nv_bfloat16 g_vtl[NH * DH * NT];
__device__ __nv_bfloat16 g_qlh[NH * LM * DH];
__device__ __nv_bfloat16 g_qll[NH * LM * DH];
__device__ __nv_bfloat16 g_klh[NH * LM * DH];
__device__ __nv_bfloat16 g_kll[NH * LM * DH];
__device__ __nv_bfloat16 g_t3th[NH * DH * LM];
__device__ __nv_bfloat16 g_t3tl[NH * DH * LM];
__device__ __nv_bfloat16 g_t4th[NH * DH * LM];
__device__ __nv_bfloat16 g_t4tl[NH * DH * LM];
// pinv bf16 buffers
__device__ __nv_bfloat16 g_a2h[NH * LM * LM];
__device__ __nv_bfloat16 g_a2l[NH * LM * LM];
__device__ __nv_bfloat16 g_zAh[NH * LM * LM];
__device__ __nv_bfloat16 g_zAl[NH * LM * LM];
__device__ __nv_bfloat16 g_zATh[NH * LM * LM];
__device__ __nv_bfloat16 g_zATl[NH * LM * LM];
__device__ __nv_bfloat16 g_zBh[NH * LM * LM];
__device__ __nv_bfloat16 g_zBl[NH * LM * LM];
__device__ __nv_bfloat16 g_zBTh[NH * LM * LM];
__device__ __nv_bfloat16 g_zBTl[NH * LM * LM];
__device__ __nv_bfloat16 g_xzh[NH * LM * LM];
__device__ __nv_bfloat16 g_xzl[NH * LM * LM];
__device__ __nv_bfloat16 g_t1Th[NH * LM * LM];
__device__ __nv_bfloat16 g_t1Tl[NH * LM * LM];
__device__ __nv_bfloat16 g_uTh[NH * LM * LM];
__device__ __nv_bfloat16 g_uTl[NH * LM * LM];
__device__ __nv_bfloat16 g_wTh[NH * LM * LM];
__device__ __nv_bfloat16 g_wTl[NH * LM * LM];

// ---------------- mma.sync / cp.async helpers ----------------
__device__ __forceinline__ uint32_t smem_u32(const void* p) {
    uint32_t a;
    asm("{ .reg .u64 t; cvta.to.shared.u64 t, %1; cvt.u32.u64 %0, t; }" : "=r"(a) : "l"(p));
    return a;
}
__device__ __forceinline__ void ldsm4(uint32_t* r, uint32_t addr) {
    asm volatile("ldmatrix.sync.aligned.m8n8.x4.shared.b16 {%0,%1,%2,%3}, [%4];"
                 : "=r"(r[0]), "=r"(r[1]), "=r"(r[2]), "=r"(r[3]) : "r"(addr));
}
__device__ __forceinline__ void mma16816(float* c, const uint32_t* a, const uint32_t* b) {
    asm volatile(
        "mma.sync.aligned.m16n8k16.row.col.f32.bf16.bf16.f32 "
        "{%0,%1,%2,%3}, {%4,%5,%6,%7}, {%8,%9}, {%0,%1,%2,%3};"
        : "+f"(c[0]), "+f"(c[1]), "+f"(c[2]), "+f"(c[3])
        : "r"(a[0]), "r"(a[1]), "r"(a[2]), "r"(a[3]), "r"(b[0]), "r"(b[1]));
}
__device__ __forceinline__ void cp16(uint32_t s, const void* g) {
    asm volatile("cp.async.cg.shared.global [%0], [%1], 16;" :: "r"(s), "l"(g));
}
#define CP_COMMIT() asm volatile("cp.async.commit_group;" ::: "memory")
#define CP_WAIT1()  asm volatile("cp.async.wait_group 1;" ::: "memory")

// ================= pipelined HMMA GEMM (bf16x3) =================
template<int WN>
__global__ void __launch_bounds__(128*WN, WN == 1 ? 3 : 2) hmma2_k(
    const __nv_bfloat16* __restrict__ Ah, const __nv_bfloat16* __restrict__ Al, int lda, long sA,
    const __nv_bfloat16* __restrict__ Bh, const __nv_bfloat16* __restrict__ Bl, int ldb, long sB,
    float* __restrict__ C, int ldc, long sC,
    int K, float alpha,
    const float* __restrict__ bias, const float* __restrict__ resid,
    __nv_bfloat16* __restrict__ Ph, __nv_bfloat16* __restrict__ Pl, int ldp, long sP,
    __nv_bfloat16* __restrict__ Th, __nv_bfloat16* __restrict__ Tl, int ldt, long sT,
    int pAux, int tAux, float auxc,
    int splitK, long splitPitch)
{
    constexpr int BN = 64 * WN;
    constexpr int THREADS = 128 * WN;
    constexpr int B1 = BN * 80;
    constexpr int STG = 20480 + 2 * B1;
    extern __shared__ char dsm[];
    const uint32_t sb0 = smem_u32(dsm);

    const int tid = threadIdx.x;
    const int wid = tid >> 5, lid = tid & 31;
    const int wm = wid & 3, wn = wid >> 2;
    const int bz = blockIdx.z;
    const int b = bz / splitK, kseg = bz - b * splitK;
    const int Kseg = K / splitK;
    const int m0 = blockIdx.y * 128, n0 = blockIdx.x * BN;

    const __nv_bfloat16* pAh = Ah + (long)b * sA;
    const __nv_bfloat16* pAl = Al + (long)b * sA;
    const __nv_bfloat16* pBh = Bh + (long)b * sB;
    const __nv_bfloat16* pBl = Bl + (long)b * sB;

    float acc[2][8][4];
    #pragma unroll
    for (int i = 0; i < 2; i++)
        #pragma unroll
        for (int j = 0; j < 8; j++)
            #pragma unroll
            for (int q = 0; q < 4; q++) acc[i][j][q] = 0.f;

    auto load = [&](int kc, int st) {
        const uint32_t sb = sb0 + st * STG;
        #pragma unroll
        for (int it = 0; it < 512 / THREADS; it++) {
            int idx = it * THREADS + tid;
            int row = idx >> 2; int cb = (idx & 3) * 16; int ce = (idx & 3) * 8;
            uint32_t so = sb + row * 80 + cb;
            const long ga = (long)(m0 + row) * lda + kc + ce;
            cp16(so,         pAh + ga);
            cp16(so + 10240, pAl + ga);
        }
        #pragma unroll
        for (int it = 0; it < (BN * 4) / THREADS; it++) {
            int idx = it * THREADS + tid;
            int row = idx >> 2; int cb = (idx & 3) * 16; int ce = (idx & 3) * 8;
            uint32_t so = sb + 20480 + row * 80 + cb;
            const long gb = (long)(n0 + row) * ldb + kc + ce;
            cp16(so,      pBh + gb);
            cp16(so + B1, pBl + gb);
        }
    };

    const int k0 = kseg * Kseg;
    const int nch = Kseg / 32;
    load(k0, 0);
    CP_COMMIT();
    for (int c = 0; c < nch; c++) {
        if (c + 1 < nch) load(k0 + (c + 1) * 32, (c + 1) & 1);
        CP_COMMIT();
        CP_WAIT1();
        __syncthreads();
        const uint32_t uAh = sb0 + (c & 1) * STG;
        const uint32_t uAl = uAh + 10240;
        const uint32_t uBh = uAh + 20480;
        const uint32_t uBl = uBh + B1;
        #pragma unroll
        for (int ks = 0; ks < 2; ks++) {
            const int k16 = ks * 16;
            uint32_t ah[2][4], al[2][4];
            #pragma unroll
            for (int mt = 0; mt < 2; mt++) {
                int r = wm * 32 + mt * 16 + (lid & 15);
                int kk = k16 + ((lid >> 4) << 3);
                uint32_t off = (uint32_t)(r * 80 + kk * 2);
                ldsm4(ah[mt], uAh + off);
                ldsm4(al[mt], uAl + off);
            }
            #pragma unroll
            for (int p = 0; p < 4; p++) {
                int r = wn * 64 + p * 16 + ((lid >> 4) << 3) + (lid & 7);
                int kk = k16 + (lid & 8);
                uint32_t off = (uint32_t)(r * 80 + kk * 2);
                uint32_t bh[4], bl[4];
                ldsm4(bh, uBh + off);
                ldsm4(bl, uBl + off);
                #pragma unroll
                for (int mt = 0; mt < 2; mt++) {
                    #pragma unroll
                    for (int s = 0; s < 2; s++) {
                        float* cc = acc[mt][p * 2 + s];
                        mma16816(cc, ah[mt], &bh[2 * s]);
                        mma16816(cc, ah[mt], &bl[2 * s]);
                        mma16816(cc, al[mt], &bh[2 * s]);
                    }
                }
            }
        }
        __syncthreads();
    }

    float* Cb = C ? (splitK > 1 ? C + (long)bz * splitPitch : C + (long)b * sC) : nullptr;
    const int tr = lid >> 2, tc = (lid & 3) * 2;
    #pragma unroll
    for (int mt = 0; mt < 2; mt++)
        #pragma unroll
        for (int nt = 0; nt < 8; nt++) {
            int row = m0 + wm * 32 + mt * 16 + tr;
            int col = n0 + wn * 64 + nt * 8 + tc;
            float vv[2][2] = {{acc[mt][nt][0] * alpha, acc[mt][nt][1] * alpha},
                              {acc[mt][nt][2] * alpha, acc[mt][nt][3] * alpha}};
            if (bias) {
                float2 bb = *(const float2*)(bias + col);
                vv[0][0] += bb.x; vv[0][1] += bb.y; vv[1][0] += bb.x; vv[1][1] += bb.y;
            }
            #pragma unroll
            for (int rr = 0; rr < 2; rr++) {
                int ro = row + rr * 8;
                if (resid) {
                    float2 r2 = *(const float2*)(resid + (long)b * sC + (long)ro * ldc + col);
                    vv[rr][0] += r2.x; vv[rr][1] += r2.y;
                }
                if (Cb) *(float2*)(Cb + (long)ro * ldc + col) = make_float2(vv[rr][0], vv[rr][1]);
                if (Ph) {
                    float p0 = vv[rr][0], p1 = vv[rr][1];
                    if (pAux) {
                        p0 = (ro == col     ? auxc : 0.f) - p0;
                        p1 = (ro == col + 1 ? auxc : 0.f) - p1;
                    }
                    __nv_bfloat16 h0 = __float2bfloat16(p0);
                    __nv_bfloat16 h1 = __float2bfloat16(p1);
                    long off = (long)b * sP + (long)ro * ldp + col;
                    *(__nv_bfloat162*)(Ph + off) = __nv_bfloat162(h0, h1);
                    *(__nv_bfloat162*)(Pl + off) =
                        __nv_bfloat162(__float2bfloat16(p0 - __bfloat162float(h0)),
                                       __float2bfloat16(p1 - __bfloat162float(h1)));
                }
                if (Th) {
                    #pragma unroll
                    for (int cc = 0; cc < 2; cc++) {
                        float tv = vv[rr][cc];
                        if (tAux) tv = (ro == col + cc ? auxc : 0.f) - tv;
                        __nv_bfloat16 hh = __float2bfloat16(tv);
                        long off = (long)b * sT + (long)(col + cc) * ldt + ro;
                        Th[off] = hh;
                        Tl[off] = __float2bfloat16(tv - __bfloat162float(hh));
                    }
                }
            }
        }
}
static const int HS1 = 2 * (20480 + 2 * 64 * 80);    // 61440
static const int HS2 = 2 * (20480 + 2 * 128 * 80);   // 81920

// ============ fused attn1 GEMM + row-softmax (WN=4, full 256-col rows) ============
// P = softmax_row(alpha * A @ B^T); emits bf16 hi/lo only. N fixed to 256 (= BN).
__global__ void __launch_bounds__(512, 1) hmma_sm1_k(
    const __nv_bfloat16* __restrict__ Ah, const __nv_bfloat16* __restrict__ Al, int lda, long sA,
    const __nv_bfloat16* __restrict__ Bh, const __nv_bfloat16* __restrict__ Bl, int ldb, long sB,
    __nv_bfloat16* __restrict__ Ph, __nv_bfloat16* __restrict__ Pl, int ldp, long sP,
    int K, float alpha)
{
    constexpr int BN = 256;
    constexpr int THREADS = 512;
    constexpr int B1 = BN * 80;          // 20480
    constexpr int STG = 20480 + 2 * B1;  // 61440
    extern __shared__ char dsm[];
    const uint32_t sb0 = smem_u32(dsm);

    const int tid = threadIdx.x;
    const int wid = tid >> 5, lid = tid & 31;
    const int wm = wid & 3, wn = wid >> 2;      // 4 m-warps x 4 n-warps
    const int b = blockIdx.z;
    const int m0 = blockIdx.y * 128;

    const __nv_bfloat16* pAh = Ah + (long)b * sA;
    const __nv_bfloat16* pAl = Al + (long)b * sA;
    const __nv_bfloat16* pBh = Bh + (long)b * sB;
    const __nv_bfloat16* pBl = Bl + (long)b * sB;

    float acc[2][8][4];
    #pragma unroll
    for (int i = 0; i < 2; i++)
        #pragma unroll
        for (int j = 0; j < 8; j++)
            #pragma unroll
            for (int q = 0; q < 4; q++) acc[i][j][q] = 0.f;

    auto load = [&](int kc, int st) {
        const uint32_t sb = sb0 + st * STG;
        {
            int idx = tid;                       // 512 threads cover 128x4 chunks
            int row = idx >> 2; int cb = (idx & 3) * 16; int ce = (idx & 3) * 8;
            uint32_t so = sb + row * 80 + cb;
            const long ga = (long)(m0 + row) * lda + kc + ce;
            cp16(so,         pAh + ga);
            cp16(so + 10240, pAl + ga);
        }
        #pragma unroll
        for (int it = 0; it < 2; it++) {         // 256x4 chunks
            int idx = it * THREADS + tid;
            int row = idx >> 2; int cb = (idx & 3) * 16; int ce = (idx & 3) * 8;
            uint32_t so = sb + 20480 + row * 80 + cb;
            const long gb = (long)row * ldb + kc + ce;
            cp16(so,      pBh + gb);
            cp16(so + B1, pBl + gb);
        }
    };

    const int nch = K / 32;
    load(0, 0);
    CP_COMMIT();
    for (int c = 0; c < nch; c++) {
        if (c + 1 < nch) load((c + 1) * 32, (c + 1) & 1);
        CP_COMMIT();
        CP_WAIT1();
        __syncthreads();
        const uint32_t uAh = sb0 + (c & 1) * STG;
        const uint32_t uAl = uAh + 10240;
        const uint32_t uBh = uAh + 20480;
        const uint32_t uBl = uBh + B1;
        #pragma unroll
        for (int ks = 0; ks < 2; ks++) {
            const int k16 = ks * 16;
            uint32_t ah[2][4], al[2][4];
            #pragma unroll
            for (int mt = 0; mt < 2; mt++) {
                int r = wm * 32 + mt * 16 + (lid & 15);
                int kk = k16 + ((lid >> 4) << 3);
                uint32_t off = (uint32_t)(r * 80 + kk * 2);
                ldsm4(ah[mt], uAh + off);
                ldsm4(al[mt], uAl + off);
            }
            #pragma unroll
            for (int p = 0; p < 4; p++) {
                int r = wn * 64 + p * 16 + ((lid >> 4) << 3) + (lid & 7);
                int kk = k16 + (lid & 8);
                uint32_t off = (uint32_t)(r * 80 + kk * 2);
                uint32_t bh[4], bl[4];
                ldsm4(bh, uBh + off);
                ldsm4(bl, uBl + off);
                #pragma unroll
                for (int mt = 0; mt < 2; mt++) {
                    #pragma unroll
                    for (int s = 0; s < 2; s++) {
                        float* cc = acc[mt][p * 2 + s];
                        mma16816(cc, ah[mt], &bh[2 * s]);
                        mma16816(cc, ah[mt], &bl[2 * s]);
                        mma16816(cc, al[mt], &bh[2 * s]);
                    }
                }
            }
        }
        __syncthreads();
    }
    // mainloop's trailing __syncthreads: smem now reusable as reduction scratch
    float* red = (float*)dsm;                    // [128 rows][4 wn]
    const int tr = lid >> 2, tc = (lid & 3) * 2;

    // scale by alpha in place
    #pragma unroll
    for (int mt = 0; mt < 2; mt++)
        #pragma unroll
        for (int nt = 0; nt < 8; nt++)
            #pragma unroll
            for (int q = 0; q < 4; q++) acc[mt][nt][q] *= alpha;

    // local row max per (mt, rr)
    float mx[2][2];
    #pragma unroll
    for (int mt = 0; mt < 2; mt++)
        #pragma unroll
        for (int rr = 0; rr < 2; rr++) {
            float m = -FLT_MAX;
            #pragma unroll
            for (int nt = 0; nt < 8; nt++) {
                m = fmaxf(m, acc[mt][nt][rr * 2 + 0]);
                m = fmaxf(m, acc[mt][nt][rr * 2 + 1]);
            }
            mx[mt][rr] = m;
        }
    #pragma unroll
    for (int o = 1; o <= 2; o <<= 1) {
        #pragma unroll
        for (int mt = 0; mt < 2; mt++)
            #pragma unroll
            for (int rr = 0; rr < 2; rr++)
                mx[mt][rr] = fmaxf(mx[mt][rr], __shfl_xor_sync(0xffffffffu, mx[mt][rr], o));
    }
    if ((lid & 3) == 0) {
        #pragma unroll
        for (int mt = 0; mt < 2; mt++)
            #pragma unroll
            for (int rr = 0; rr < 2; rr++)
                red[(wm * 32 + mt * 16 + rr * 8 + tr) * 4 + wn] = mx[mt][rr];
    }
    __syncthreads();
    float rowmax[2][2];
    #pragma unroll
    for (int mt = 0; mt < 2; mt++)
        #pragma unroll
        for (int rr = 0; rr < 2; rr++) {
            const float* rp = red + (wm * 32 + mt * 16 + rr * 8 + tr) * 4;
            rowmax[mt][rr] = fmaxf(fmaxf(rp[0], rp[1]), fmaxf(rp[2], rp[3]));
        }
    __syncthreads();     // before reusing red for sums

    // exp + local sum
    float sm[2][2] = {{0.f, 0.f}, {0.f, 0.f}};
    #pragma unroll
    for (int mt = 0; mt < 2; mt++)
        #pragma unroll
        for (int nt = 0; nt < 8; nt++)
            #pragma unroll
            for (int rr = 0; rr < 2; rr++) {
                float e0 = __expf(acc[mt][nt][rr * 2 + 0] - rowmax[mt][rr]);
                float e1 = __expf(acc[mt][nt][rr * 2 + 1] - rowmax[mt][rr]);
                acc[mt][nt][rr * 2 + 0] = e0;
                acc[mt][nt][rr * 2 + 1] = e1;
                sm[mt][rr] += e0 + e1;
            }
    #pragma unroll
    for (int o = 1; o <= 2; o <<= 1) {
        #pragma unroll
        for (int mt = 0; mt < 2; mt++)
            #pragma unroll
            for (int rr = 0; rr < 2; rr++)
                sm[mt][rr] += __shfl_xor_sync(0xffffffffu, sm[mt][rr], o);
    }
    if ((lid & 3) == 0) {
        #pragma unroll
        for (int mt = 0; mt < 2; mt++)
            #pragma unroll
            for (int rr = 0; rr < 2; rr++)
                red[(wm * 32 + mt * 16 + rr * 8 + tr) * 4 + wn] = sm[mt][rr];
    }
    __syncthreads();
    float inv[2][2];
    #pragma unroll
    for (int mt = 0; mt < 2; mt++)
        #pragma unroll
        for (int rr = 0; rr < 2; rr++) {
            const float* rp = red + (wm * 32 + mt * 16 + rr * 8 + tr) * 4;
            inv[mt][rr] = 1.f / (rp[0] + rp[1] + rp[2] + rp[3]);
        }

    // emit bf16 hi/lo probabilities
    #pragma unroll
    for (int mt = 0; mt < 2; mt++)
        #pragma unroll
        for (int nt = 0; nt < 8; nt++) {
            int col = wn * 64 + nt * 8 + tc;
            #pragma unroll
            for (int rr = 0; rr < 2; rr++) {
                int rg = m0 + wm * 32 + mt * 16 + rr * 8 + tr;
                float p0 = acc[mt][nt][rr * 2 + 0] * inv[mt][rr];
                float p1 = acc[mt][nt][rr * 2 + 1] * inv[mt][rr];
                __nv_bfloat16 h0 = __float2bfloat16(p0);
                __nv_bfloat16 h1 = __float2bfloat16(p1);
                long off = (long)b * sP + (long)rg * ldp + col;
                *(__nv_bfloat162*)(Ph + off) = __nv_bfloat162(h0, h1);
                *(__nv_bfloat162*)(Pl + off) =
                    __nv_bfloat162(__float2bfloat16(p0 - __bfloat162float(h0)),
                                   __float2bfloat16(p1 - __bfloat162float(h1)));
            }
        }
}
static const int HSM = 2 * 61440;   // 122880

// ---------------- bf16 split prep kernels ----------------
__global__ void split_k(const float* __restrict__ x, __nv_bfloat16* __restrict__ h,
                        __nv_bfloat16* __restrict__ l, int n4)
{
    int i = blockIdx.x * 256 + threadIdx.x;
    if (i >= n4) return;
    float4 v = ((const float4*)x)[i];
    __nv_bfloat16 h0 = __float2bfloat16(v.x), h1 = __float2bfloat16(v.y);
    __nv_bfloat16 h2 = __float2bfloat16(v.z), h3 = __float2bfloat16(v.w);
    __nv_bfloat162* hp = (__nv_bfloat162*)h;
    __nv_bfloat162* lp = (__nv_bfloat162*)l;
    hp[i*2]   = __nv_bfloat162(h0, h1);
    hp[i*2+1] = __nv_bfloat162(h2, h3);
    lp[i*2]   = __nv_bfloat162(__float2bfloat16(v.x - __bfloat162float(h0)),
                               __float2bfloat16(v.y - __bfloat162float(h1)));
    lp[i*2+1] = __nv_bfloat162(__float2bfloat16(v.z - __bfloat162float(h2)),
                               __float2bfloat16(v.w - __bfloat162float(h3)));
}
__global__ void splitT_k(const float* __restrict__ w, __nv_bfloat16* __restrict__ h,
                         __nv_bfloat16* __restrict__ l, int K, int N)
{
    int idx = blockIdx.x * 256 + threadIdx.x;
    if (idx >= N * K) return;
    int n = idx / K, k = idx - n * K;
    float v = w[(long)k * N + n];
    __nv_bfloat16 hb = __float2bfloat16(v);
    h[idx] = hb;
    l[idx] = __float2bfloat16(v - __bfloat162float(hb));
}
__global__ void vT_split_k(const float* __restrict__ qkv,
                           __nv_bfloat16* __restrict__ vh, __nv_bfloat16* __restrict__ vl)
{
    __shared__ float tile[64][65];
    int h = blockIdx.y, n0 = blockIdx.x * 64;
    int tid = threadIdx.x;
    for (int i = tid; i < 64 * 64; i += 256) {
        int r = i >> 6, c = i & 63;
        tile[r][c] = qkv[(long)(n0 + r) * (3*DM) + 2*DM + h * DH + c];
    }
    __syncthreads();
    for (int i = tid; i < 64 * 64; i += 256) {
        int c = i >> 6, r = i & 63;
        float v = tile[r][c];
        __nv_bfloat16 hb = __float2bfloat16(v);
        long off = ((long)h * DH + c) * NT + n0 + r;
        vh[off] = hb;
        vl[off] = __float2bfloat16(v - __bfloat162float(hb));
    }
}
// fused: reduce 16 split-K partials of t3 AND emit transposed bf16 hi/lo
__global__ void reduce_t3T(const float* __restrict__ part,
                           __nv_bfloat16* __restrict__ th, __nv_bfloat16* __restrict__ tl)
{
    int idx = blockIdx.x * 256 + threadIdx.x;
    if (idx >= NH * DH * LM) return;
    int h = idx >> 14, c = (idx >> 8) & 63, m = idx & 255;
    float s = 0.f;
    const float* p = part + ((long)h * 16 << 14) + (m << 6) + c;
    #pragma unroll
    for (int ss = 0; ss < 16; ss++) s += p[(long)ss << 14];
    __nv_bfloat16 hb = __float2bfloat16(s);
    th[idx] = hb;
    tl[idx] = __float2bfloat16(s - __bfloat162float(hb));
}
// z0 = a2^T * s
__global__ void pinv_init2(const float* __restrict__ a2, const float* __restrict__ sc,
                           __nv_bfloat16* __restrict__ zh, __nv_bfloat16* __restrict__ zl,
                           __nv_bfloat16* __restrict__ zth, __nv_bfloat16* __restrict__ ztl)
{
    int idx = blockIdx.x * 256 + threadIdx.x;
    int h = idx >> 16, r = (idx >> 8) & 255, c = idx & 255;
    float s = sc[0];
    float vt = a2[idx] * s;
    float vn = a2[(h << 16) + (c << 8) + r] * s;
    __nv_bfloat16 hn = __float2bfloat16(vn), ht = __float2bfloat16(vt);
    zh[idx] = hn; zl[idx] = __float2bfloat16(vn - __bfloat162float(hn));
    zth[idx] = ht; ztl[idx] = __float2bfloat16(vt - __bfloat162float(ht));
}

// ---------------- f32x2 helpers (SIMT gemm for attn2) ----------------
__device__ __forceinline__ unsigned long long dup2(float x) {
    unsigned long long r;
    asm("mov.b64 %0, {%1, %1};" : "=l"(r) : "f"(x));
    return r;
}
__device__ __forceinline__ void fma2(unsigned long long& d, unsigned long long a, unsigned long long b) {
    asm("fma.rn.f32x2 %0, %1, %2, %0;" : "+l"(d) : "l"(a), "l"(b));
}
__device__ __forceinline__ void unpack2(unsigned long long v, float& lo, float& hi) {
    asm("mov.b64 {%0, %1}, %2;" : "=f"(lo), "=f"(hi) : "l"(v));
}

// ---------------- reductions ----------------
__device__ __forceinline__ float warpSum(float v) {
    #pragma unroll
    for (int o = 16; o; o >>= 1) v += __shfl_xor_sync(0xffffffffu, v, o);
    return v;
}
__device__ __forceinline__ float warpMax(float v) {
    #pragma unroll
    for (int o = 16; o; o >>= 1) v = fmaxf(v, __shfl_xor_sync(0xffffffffu, v, o));
    return v;
}
__device__ float blockSum(float v) {
    __shared__ float sh[33];
    int lane = threadIdx.x & 31, wid = threadIdx.x >> 5;
    v = warpSum(v);
    __syncthreads();
    if (lane == 0) sh[wid] = v;
    __syncthreads();
    int nw = blockDim.x >> 5;
    float r = (wid == 0 && lane < nw) ? sh[lane] : 0.f;
    if (wid == 0) { r = warpSum(r); if (lane == 0) sh[32] = r; }
    __syncthreads();
    return sh[32];
}
__device__ float blockMax(float v) {
    __shared__ float sh[33];
    int lane = threadIdx.x & 31, wid = threadIdx.x >> 5;
    v = warpMax(v);
    __syncthreads();
    if (lane == 0) sh[wid] = v;
    __syncthreads();
    int nw = blockDim.x >> 5;
    float r = (wid == 0 && lane < nw) ? sh[lane] : -FLT_MAX;
    if (wid == 0) { r = warpMax(r); if (lane == 0) sh[32] = r; }
    __syncthreads();
    return sh[32];
}

// ---------------- SIMT GEMM (attn2 only) ----------------
template<int BM, int BN, int BK, int TM, int TN, bool TB>
__global__ __launch_bounds__((BM/TM)*(BN/TN))
void gemm_k(const float* __restrict__ A, int lda, long sA,
            const float* __restrict__ B, int ldb, long sB,
            float* __restrict__ C, int ldc, long sC,
            int K, float alpha)
{
    constexpr int THREADS = (BM/TM)*(BN/TN);
    __shared__ __align__(16) float As[BM][BK + 4];
    __shared__ __align__(16) float Bs[BK][BN + 4];
    const int tid = threadIdx.x;
    const int batch = blockIdx.z;
    const int m0 = blockIdx.y * BM, n0 = blockIdx.x * BN;
    const float* Ab = A + (long)batch * sA + (long)m0 * lda;
    const float* Bb = B + (long)batch * sB;

    unsigned long long acc[TM][TN/2];
    #pragma unroll
    for (int i = 0; i < TM; i++)
        #pragma unroll
        for (int j = 0; j < TN/2; j++) acc[i][j] = 0ull;

    const int tx = tid % (BN/TN), ty = tid / (BN/TN);

    for (int k0 = 0; k0 < K; k0 += BK) {
        #pragma unroll
        for (int idx = tid; idx < BM*(BK/4); idx += THREADS) {
            int m = idx / (BK/4), kq = idx - m * (BK/4);
            float4 v = *(const float4*)(Ab + (long)m * lda + k0 + kq*4);
            *(float4*)&As[m][kq*4] = v;
        }
        if (!TB) {
            #pragma unroll
            for (int idx = tid; idx < BK*(BN/4); idx += THREADS) {
                int kk = idx / (BN/4), nq = idx - kk * (BN/4);
                float4 v = *(const float4*)(Bb + (long)(k0+kk) * ldb + n0 + nq*4);
                *(float4*)&Bs[kk][nq*4] = v;
            }
        } else {
            #pragma unroll
            for (int idx = tid; idx < BN*(BK/4); idx += THREADS) {
                int n = idx / (BK/4), kq = idx - n * (BK/4);
                float4 v = *(const float4*)(Bb + (long)(n0+n) * ldb + k0 + kq*4);
                Bs[kq*4+0][n] = v.x; Bs[kq*4+1][n] = v.y;
                Bs[kq*4+2][n] = v.z; Bs[kq*4+3][n] = v.w;
            }
        }
        __syncthreads();
        #pragma unroll
        for (int kk = 0; kk < BK; kk++) {
            unsigned long long bb[TN/2];
            #pragma unroll
            for (int q = 0; q < TN/4; q++) {
                ulonglong2 bv = *(const ulonglong2*)&Bs[kk][tx*TN + q*4];
                bb[q*2]   = bv.x;
                bb[q*2+1] = bv.y;
            }
            #pragma unroll
            for (int i = 0; i < TM; i++) {
                unsigned long long aa = dup2(As[ty*TM + i][kk]);
                #pragma unroll
                for (int j = 0; j < TN/2; j++) fma2(acc[i][j], aa, bb[j]);
            }
        }
        __syncthreads();
    }

    float* Cb = C + (long)batch * sC;
    #pragma unroll
    for (int i = 0; i < TM; i++) {
        int m = m0 + ty*TM + i;
        #pragma unroll
        for (int j = 0; j < TN/2; j++) {
            float lo, hi;
            unpack2(acc[i][j], lo, hi);
            Cb[(long)m * ldc + n0 + tx*TN + 2*j]     = alpha * lo;
            Cb[(long)m * ldc + n0 + tx*TN + 2*j + 1] = alpha * hi;
        }
    }
}

// ---------------- landmarks ----------------
__global__ void landmarks_k(const float* __restrict__ qkv, float* __restrict__ ql, float* __restrict__ kl,
                            __nv_bfloat16* __restrict__ qlh, __nv_bfloat16* __restrict__ qll,
                            __nv_bfloat16* __restrict__ klh, __nv_bfloat16* __restrict__ kll)
{
    int hm = blockIdx.x;
    int h = hm >> 8, mm = hm & 255;
    int d = threadIdx.x;
    const float* base = qkv + (long)(mm * 32) * (3*DM) + h * DH + d;
    float sq = 0.f, sk = 0.f;
    #pragma unroll 8
    for (int r = 0; r < 32; r++) { sq += base[r * (3*DM)]; sk += base[r * (3*DM) + DM]; }
    float q = sq * (1.f / 32.f) * 0.125f;
    float k = sk * (1.f / 32.f);
    int o = hm * DH + d;
    ql[o] = q; kl[o] = k;
    __nv_bfloat16 qh = __float2bfloat16(q), kh = __float2bfloat16(k);
    qlh[o] = qh; qll[o] = __float2bfloat16(q - __bfloat162float(qh));
    klh[o] = kh; kll[o] = __float2bfloat16(k - __bfloat162float(kh));
}

// ---------------- softmaxes ----------------
__device__ __forceinline__ void store_split4(__nv_bfloat16* ph, __nv_bfloat16* pl, float4 v)
{
    __nv_bfloat16 h0 = __float2bfloat16(v.x), h1 = __float2bfloat16(v.y);
    __nv_bfloat16 h2 = __float2bfloat16(v.z), h3 = __float2bfloat16(v.w);
    *(__nv_bfloat162*)ph = __nv_bfloat162(h0, h1);
    *(__nv_bfloat162*)(ph+2) = __nv_bfloat162(h2, h3);
    *(__nv_bfloat162*)pl = __nv_bfloat162(__float2bfloat16(v.x - __bfloat162float(h0)),
                                          __float2bfloat16(v.y - __bfloat162float(h1)));
    *(__nv_bfloat162*)(pl+2) = __nv_bfloat162(__float2bfloat16(v.z - __bfloat162float(h2)),
                                              __float2bfloat16(v.w - __bfloat162float(h3)));
}

__global__ void softmax256(float* __restrict__ d, __nv_bfloat16* __restrict__ oh, __nv_bfloat16* __restrict__ ol)
{
    int warp = threadIdx.x >> 5, lane = threadIdx.x & 31;
    long row = (long)blockIdx.x * 8 + warp;
    float* p = d + row * 256;
    float4 v0 = *(float4*)(p + lane*4);
    float4 v1 = *(float4*)(p + 128 + lane*4);
    float mx = fmaxf(fmaxf(fmaxf(v0.x, v0.y), fmaxf(v0.z, v0.w)),
                     fmaxf(fmaxf(v1.x, v1.y), fmaxf(v1.z, v1.w)));
    mx = warpMax(mx);
    v0.x = __expf(v0.x - mx); v0.y = __expf(v0.y - mx);
    v0.z = __expf(v0.z - mx); v0.w = __expf(v0.w - mx);
    v1.x = __expf(v1.x - mx); v1.y = __expf(v1.y - mx);
    v1.z = __expf(v1.z - mx); v1.w = __expf(v1.w - mx);
    float s = v0.x + v0.y + v0.z + v0.w + v1.x + v1.y + v1.z + v1.w;
    s = warpSum(s);
    float inv = 1.f / s;
    v0.x *= inv; v0.y *= inv; v0.z *= inv; v0.w *= inv;
    v1.x *= inv; v1.y *= inv; v1.z *= inv; v1.w *= inv;
    if (oh) {
        store_split4(oh + row*256 + lane*4, ol + row*256 + lane*4, v0);
        store_split4(oh + row*256 + 128 + lane*4, ol + row*256 + 128 + lane*4, v1);
    } else {
        *(float4*)(p + lane*4) = v0;
        *(float4*)(p + 128 + lane*4) = v1;
    }
}

__global__ __launch_bounds__(256)
void softmax8192(float* __restrict__ d, __nv_bfloat16* __restrict__ oh, __nv_bfloat16* __restrict__ ol)
{
    long rb = (long)blockIdx.x * 8192;
    float* p = d + rb;
    int t = threadIdx.x;
    float4 v[8];
    float mx = -FLT_MAX;
    #pragma unroll
    for (int q = 0; q < 8; q++) {
        v[q] = *(float4*)(p + (q*256 + t)*4);
        mx = fmaxf(mx, fmaxf(fmaxf(v[q].x, v[q].y), fmaxf(v[q].z, v[q].w)));
    }
    mx = blockMax(mx);
    float s = 0.f;
    #pragma unroll
    for (int q = 0; q < 8; q++) {
        v[q].x = __expf(v[q].x - mx); v[q].y = __expf(v[q].y - mx);
        v[q].z = __expf(v[q].z - mx); v[q].w = __expf(v[q].w - mx);
        s += v[q].x + v[q].y + v[q].z + v[q].w;
    }
    s = blockSum(s);
    float inv = 1.f / s;
    #pragma unroll
    for (int q = 0; q < 8; q++) {
        v[q].x *= inv; v[q].y *= inv; v[q].z *= inv; v[q].w *= inv;
        store_split4(oh + rb + (q*256 + t)*4, ol + rb + (q*256 + t)*4, v[q]);
    }
}

// ---------------- pinv scale helpers ----------------
__global__ void absmax_sums(const float* __restrict__ x, float* __restrict__ rs, float* __restrict__ cs)
{
    int h = blockIdx.x, t = threadIdx.x;
    const float* base = x + (long)h * LM * LM;
    float r = 0.f;
    const float* rp = base + (long)t * LM;
    #pragma unroll 8
    for (int i = 0; i < LM; i++) r += fabsf(rp[i]);
    rs[h * LM + t] = r;
    float c = 0.f;
    const float* cp = base + t;
    #pragma unroll 8
    for (int i = 0; i < LM; i++) c += fabsf(cp[i * LM]);
    cs[h * LM + t] = c;
}
__global__ void calc_scale(const float* __restrict__ rs, const float* __restrict__ cs, float* __restrict__ sc)
{
    float mr = -FLT_MAX, mc = -FLT_MAX;
    for (int i = threadIdx.x; i < NH * LM; i += blockDim.x) {
        mr = fmaxf(mr, rs[i]); mc = fmaxf(mc, cs[i]);
    }
    mr = blockMax(mr); mc = blockMax(mc);
    if (threadIdx.x == 0) sc[0] = 1.f / (mr * mc);
}

// ---------------- depthwise conv (standalone result buffer) ----------------
__global__ void conv_store_k(const float* __restrict__ qkv, const float* __restrict__ cw,
                             float* __restrict__ convres)
{
    __shared__ float ws[NH * CK];
    for (int t = threadIdx.x; t < NH * CK; t += blockDim.x) ws[t] = cw[t];
    __syncthreads();
    int idx = blockIdx.x * blockDim.x + threadIdx.x;
    if (idx >= NT * DM) return;
    int c = idx & (DM - 1);
    int n = idx >> 9;
    int h = c >> 6;
    const float* wrow = ws + h * CK;
    float acc = 0.f;
    #pragma unroll
    for (int k = 0; k < CK; k++) {
        int nn = n - (CK/2) + k;
        if (nn >= 0 && nn < NT) acc += wrow[k] * qkv[(long)nn * (3*DM) + 2*DM + c];
    }
    convres[idx] = acc;
}

// ---------------- A_raw ----------------
__global__ void araw_k(const float* __restrict__ adj, const float* __restrict__ q2,
                       const float* __restrict__ k2, float* __restrict__ Araw)
{
    int i = blockIdx.x;
    __shared__ float qs[ATTD];
    qs[threadIdx.x] = q2[(long)i * ATTD + threadIdx.x];
    __syncthreads();
    float acc = 0.f;
    const float4* arow = (const float4*)(adj + (long)i * NT);
    const float4* q4 = (const float4*)qs;
    for (int t = threadIdx.x; t < NT/4; t += blockDim.x) {
        float4 a4 = arow[t];
        float av[4] = {a4.x, a4.y, a4.z, a4.w};
        #pragma unroll
        for (int c = 0; c < 4; c++) {
            if (av[c] != 0.f) {
                int j = t * 4 + c;
                const float4* k4 = (const float4*)(k2 + (long)j * ATTD);
                float dot = 0.f;
                #pragma unroll 8
                for (int d = 0; d < ATTD/4; d++) {
                    float4 a = q4[d], b = k4[d];
                    dot += a.x*b.x + a.y*b.y + a.z*b.z + a.w*b.w;
                }
                acc += av[c] * dot;
            }
        }
    }
    acc = blockSum(acc);
    if (threadIdx.x == 0) Araw[i] = acc * (1.f / 16.f);
}

__global__ void alpha_softmax_k(const float* __restrict__ Araw, float* __restrict__ alpha)
{
    float mx = -FLT_MAX;
    for (int i = threadIdx.x; i < NT; i += blockDim.x) mx = fmaxf(mx, Araw[i]);
    mx = blockMax(mx);
    float s = 0.f;
    for (int i = threadIdx.x; i < NT; i += blockDim.x) {
        float e = __expf(Araw[i] - mx); alpha[i] = e; s += e;
    }
    s = blockSum(s);
    float inv = 1.f / s;
    for (int i = threadIdx.x; i < NT; i += blockDim.x) alpha[i] *= inv;
}

// ---------------- final elementwise ----------------
__global__ void final_k(const float* __restrict__ val, const float* __restrict__ enc,
                        const float* __restrict__ alpha, const float* __restrict__ Araw,
                        float* __restrict__ out)
{
    int idx = blockIdx.x * blockDim.x + threadIdx.x;
    if (idx >= NT * DM) return;
    int n = idx >> 9;
    float xl = alpha[n] * val[idx];
    float wei = 1.f / (1.f + __expf(xl));
    float sq = wei * wei;
    out[idx] = xl * 2.f * sq + 2.f * enc[idx] * (1.f - sq);
    if (idx < NT) out[(long)NT * DM + idx] = Araw[idx];
}

// ---------------- host ----------------
#define GEMM_MED_T gemm_k<64,64,16,4,4,true>
#define NB16 (__nv_bfloat16*)nullptr
#define F32N (float*)nullptr

// Streams/events created exactly once on first call (correctness run, before the
// harness's pre-capture memory baseline); reused every call thereafter.
struct SideCtx {
    cudaStream_t s1, s2;
    cudaEvent_t evStart, ev0, evW, evQkv, evLm, evZ, evVal, evConv, evVT, evEnc, evK2;
    SideCtx() {
        cudaStreamCreateWithFlags(&s1, cudaStreamNonBlocking);
        cudaStreamCreateWithFlags(&s2, cudaStreamNonBlocking);
        cudaEventCreateWithFlags(&evStart, cudaEventDisableTiming);
        cudaEventCreateWithFlags(&ev0, cudaEventDisableTiming);
        cudaEventCreateWithFlags(&evW, cudaEventDisableTiming);
        cudaEventCreateWithFlags(&evQkv, cudaEventDisableTiming);
        cudaEventCreateWithFlags(&evLm, cudaEventDisableTiming);
        cudaEventCreateWithFlags(&evZ, cudaEventDisableTiming);
        cudaEventCreateWithFlags(&evVal, cudaEventDisableTiming);
        cudaEventCreateWithFlags(&evConv, cudaEventDisableTiming);
        cudaEventCreateWithFlags(&evVT, cudaEventDisableTiming);
        cudaEventCreateWithFlags(&evEnc, cudaEventDisableTiming);
        cudaEventCreateWithFlags(&evK2, cudaEventDisableTiming);
    }
};

extern "C" void kernel_launch(void* const* d_in, const int* in_sizes, int n_in,
                              void* d_out, int out_size)
{
    static SideCtx ctx;
    cudaStream_t s1 = ctx.s1, s2 = ctx.s2;

    const float* dense = (const float*)d_in[0];
    const float* adj   = (const float*)d_in[1];
    const float* wq    = (const float*)d_in[2];
    const float* wk    = (const float*)d_in[3];
    const float* wv_w  = (const float*)d_in[4];
    const float* wv_b  = (const float*)d_in[5];
    const float* qkv_w = (const float*)d_in[6];
    const float* out_w = (const float*)d_in[7];
    const float* out_b = (const float*)d_in[8];
    const float* conv_w= (const float*)d_in[9];
    float* out = (float*)d_out;

    float *qkv, *ql, *kl, *a3, *a2, *t3p, *convres, *enc, *q2, *k2, *val;
    float *Araw, *alpha, *rs, *cs, *sc;
    __nv_bfloat16 *dh, *dl, *th, *tl, *ench, *encl, *wth, *wtl, *wvth, *wvtl;
    __nv_bfloat16 *woth, *wotl, *wqth, *wqtl, *wkth, *wktl, *qkvh, *qkvl;
    __nv_bfloat16 *a1h, *a1l, *a3h, *a3l, *vth, *vtl, *qlh, *qll, *klh, *kll;
    __nv_bfloat16 *t3th, *t3tl, *t4th, *t4tl;
    __nv_bfloat16 *a2h, *a2l, *zAh, *zAl, *zATh, *zATl, *zBh, *zBl, *zBTh, *zBTl;
    __nv_bfloat16 *xzh, *xzl, *t1Th, *t1Tl, *uTh, *uTl, *wTh, *wTl;
    cudaGetSymbolAddress((void**)&qkv, g_qkv);
    cudaGetSymbolAddress((void**)&ql, g_ql);
    cudaGetSymbolAddress((void**)&kl, g_kl);
    cudaGetSymbolAddress((void**)&a3, g_attn3);
    cudaGetSymbolAddress((void**)&a2, g_attn2);
    cudaGetSymbolAddress((void**)&t3p, g_t3p);
    cudaGetSymbolAddress((void**)&convres, g_convres);
    cudaGetSymbolAddress((void**)&enc, g_enc);
    cudaGetSymbolAddress((void**)&q2, g_q2);
    cudaGetSymbolAddress((void**)&k2, g_k2);
    cudaGetSymbolAddress((void**)&val, g_val);
    cudaGetSymbolAddress((void**)&Araw, g_Araw);
    cudaGetSymbolAddress((void**)&alpha, g_alpha);
    cudaGetSymbolAddress((void**)&rs, g_rs);
    cudaGetSymbolAddress((void**)&cs, g_cs);
    cudaGetSymbolAddress((void**)&sc, g_scale);
    cudaGetSymbolAddress((void**)&dh, g_dh);
    cudaGetSymbolAddress((void**)&dl, g_dl);
    cudaGetSymbolAddress((void**)&th, g_th);
    cudaGetSymbolAddress((void**)&tl, g_tl);
    cudaGetSymbolAddress((void**)&ench, g_ench);
    cudaGetSymbolAddress((void**)&encl, g_encl);
    cudaGetSymbolAddress((void**)&wth, g_wth);
    cudaGetSymbolAddress((void**)&wtl, g_wtl);
    cudaGetSymbolAddress((void**)&wvth, g_wvth);
    cudaGetSymbolAddress((void**)&wvtl, g_wvtl);
    cudaGetSymbolAddress((void**)&woth, g_woth);
    cudaGetSymbolAddress((void**)&wotl, g_wotl);
    cudaGetSymbolAddress((void**)&wqth, g_wqth);
    cudaGetSymbolAddress((void**)&wqtl, g_wqtl);
    cudaGetSymbolAddress((void**)&wkth, g_wkth);
    cudaGetSymbolAddress((void**)&wktl, g_wktl);
    cudaGetSymbolAddress((void**)&qkvh, g_qkvh);
    cudaGetSymbolAddress((void**)&qkvl, g_qkvl);
    cudaGetSymbolAddress((void**)&a1h, g_a1h);
    cudaGetSymbolAddress((void**)&a1l, g_a1l);
    cudaGetSymbolAddress((void**)&a3h, g_a3h);
    cudaGetSymbolAddress((void**)&a3l, g_a3l);
    cudaGetSymbolAddress((void**)&vth, g_vth);
    cudaGetSymbolAddress((void**)&vtl, g_vtl);
    cudaGetSymbolAddress((void**)&qlh, g_qlh);
    cudaGetSymbolAddress((void**)&qll, g_qll);
    cudaGetSymbolAddress((void**)&klh, g_klh);
    cudaGetSymbolAddress((void**)&kll, g_kll);
    cudaGetSymbolAddress((void**)&t3th, g_t3th);
    cudaGetSymbolAddress((void**)&t3tl, g_t3tl);
    cudaGetSymbolAddress((void**)&t4th, g_t4th);
    cudaGetSymbolAddress((void**)&t4tl, g_t4tl);
    cudaGetSymbolAddress((void**)&a2h, g_a2h);
    cudaGetSymbolAddress((void**)&a2l, g_a2l);
    cudaGetSymbolAddress((void**)&zAh, g_zAh);
    cudaGetSymbolAddress((void**)&zAl, g_zAl);
    cudaGetSymbolAddress((void**)&zATh, g_zATh);
    cudaGetSymbolAddress((void**)&zATl, g_zATl);
    cudaGetSymbolAddress((void**)&zBh, g_zBh);
    cudaGetSymbolAddress((void**)&zBl, g_zBl);
    cudaGetSymbolAddress((void**)&zBTh, g_zBTh);
    cudaGetSymbolAddress((void**)&zBTl, g_zBTl);
    cudaGetSymbolAddress((void**)&xzh, g_xzh);
    cudaGetSymbolAddress((void**)&xzl, g_xzl);
    cudaGetSymbolAddress((void**)&t1Th, g_t1Th);
    cudaGetSymbolAddress((void**)&t1Tl, g_t1Tl);
    cudaGetSymbolAddress((void**)&uTh, g_uTh);
    cudaGetSymbolAddress((void**)&uTl, g_uTl);
    cudaGetSymbolAddress((void**)&wTh, g_wTh);
    cudaGetSymbolAddress((void**)&wTl, g_wTl);

    cudaFuncSetAttribute(hmma2_k<1>, cudaFuncAttributeMaxDynamicSharedMemorySize, HS1);
    cudaFuncSetAttribute(hmma2_k<2>, cudaFuncAttributeMaxDynamicSharedMemorySize, HS2);
    cudaFuncSetAttribute(hmma_sm1_k, cudaFuncAttributeMaxDynamicSharedMemorySize, HSM);

    const long HL = (long)LM * LM;

    // fork point: both side streams join the capture graph via this event
    cudaEventRecord(ctx.evStart, 0);
    cudaStreamWaitEvent(s1, ctx.evStart, 0);
    cudaStreamWaitEvent(s2, ctx.evStart, 0);

    // --- s1 head: input-only weight splits (out_w, wq, wk) ---
    splitT_k<<<(DM*DM + 255)/256, 256, 0, s1>>>(out_w, woth, wotl, DM, DM);
    splitT_k<<<(DM*ATTD + 255)/256, 256, 0, s1>>>(wq, wqth, wqtl, DM, ATTD);
    splitT_k<<<(DM*ATTD + 255)/256, 256, 0, s1>>>(wk, wkth, wktl, DM, ATTD);
    cudaEventRecord(ctx.evW, s1);

    // --- s2 head: wv split (input-only) ---
    splitT_k<<<(DM*DM + 255)/256, 256, 0, s2>>>(wv_w, wvth, wvtl, DM, DM);

    // 1. split dense (main); s2 then runs val GEMM
    split_k<<<(NT*DM/4 + 255)/256, 256>>>(dense, dh, dl, NT*DM/4);
    cudaEventRecord(ctx.ev0, 0);
    cudaStreamWaitEvent(s2, ctx.ev0, 0);
    hmma2_k<2><<<dim3(4, 64, 1), 256, HS2, s2>>>(dh, dl, DM, 0, wvth, wvtl, DM, 0,
        val, DM, 0, DM, 1.f, wv_b, nullptr, NB16, NB16, 0, 0, NB16, NB16, 0, 0, 0, 0, 0.f, 1, 0);
    cudaEventRecord(ctx.evVal, s2);

    // main: qkv = dense @ qkv_w
    splitT_k<<<(3*DM*DM + 255)/256, 256>>>(qkv_w, wth, wtl, DM, 3*DM);
    hmma2_k<2><<<dim3(12, 64, 1), 256, HS2>>>(dh, dl, DM, 0, wth, wtl, DM, 0,
        qkv, 3*DM, 0, DM, 1.f, nullptr, nullptr,
        qkvh, qkvl, 3*DM, 0, NB16, NB16, 0, 0, 0, 0, 0.f, 1, 0);
    cudaEventRecord(ctx.evQkv, 0);

    // s2 (after qkv): vT split + depthwise conv into convres
    cudaStreamWaitEvent(s2, ctx.evQkv, 0);
    vT_split_k<<<dim3(NT/64, NH), 256, 0, s2>>>(qkv, vth, vtl);
    cudaEventRecord(ctx.evVT, s2);
    conv_store_k<<<(NT*DM + 255)/256, 256, 0, s2>>>(qkv, conv_w, convres);
    cudaEventRecord(ctx.evConv, s2);

    // 2. landmarks; fork s1 for the pinv chain
    landmarks_k<<<NH*LM, DH>>>(qkv, ql, kl, qlh, qll, klh, kll);
    cudaEventRecord(ctx.evLm, 0);
    cudaStreamWaitEvent(s1, ctx.evLm, 0);

    // --- s1: attn2 + pinv Newton-Schulz ---
    GEMM_MED_T<<<dim3(LM/64, LM/64, NH), 256, 0, s1>>>(
        ql, DH, (long)LM*DH, kl, DH, (long)LM*DH, a2, LM, HL, DH, 1.f);
    softmax256<<<NH*LM/8, 256, 0, s1>>>(a2, nullptr, nullptr);
    absmax_sums<<<NH, 256, 0, s1>>>(a2, rs, cs);
    calc_scale<<<1, 256, 0, s1>>>(rs, cs, sc);
    split_k<<<NH*LM*LM/4/256, 256, 0, s1>>>(a2, a2h, a2l, NH*LM*LM/4);
    pinv_init2<<<NH*LM*LM/256, 256, 0, s1>>>(a2, sc, zAh, zAl, zATh, zATl);

    __nv_bfloat16 *zinh = zAh, *zinl = zAl, *zinTh = zATh, *zinTl = zATl;
    __nv_bfloat16 *zoth = zBh, *zotl = zBl, *zotTh = zBTh, *zotTl = zBTl;
    const dim3 pgrid(4, 2, NH);
    for (int it = 0; it < 6; it++) {
        hmma2_k<1><<<pgrid, 128, HS1, s1>>>(a2h, a2l, LM, HL, zinTh, zinTl, LM, HL,
            F32N, 0, 0, LM, 1.f, nullptr, nullptr,
            xzh, xzl, LM, HL, t1Th, t1Tl, LM, HL, 0, 1, 7.f, 1, 0);
        hmma2_k<1><<<pgrid, 128, HS1, s1>>>(xzh, xzl, LM, HL, t1Th, t1Tl, LM, HL,
            F32N, 0, 0, LM, 1.f, nullptr, nullptr,
            NB16, NB16, 0, 0, uTh, uTl, LM, HL, 0, 1, 15.f, 1, 0);
        hmma2_k<1><<<pgrid, 128, HS1, s1>>>(xzh, xzl, LM, HL, uTh, uTl, LM, HL,
            F32N, 0, 0, LM, 1.f, nullptr, nullptr,
            NB16, NB16, 0, 0, wTh, wTl, LM, HL, 0, 1, 13.f, 1, 0);
        hmma2_k<1><<<pgrid, 128, HS1, s1>>>(zinh, zinl, LM, HL, wTh, wTl, LM, HL,
            F32N, 0, 0, LM, 0.25f, nullptr, nullptr,
            zoth, zotl, LM, HL, zotTh, zotTl, LM, HL, 0, 0, 0.f, 1, 0);
        __nv_bfloat16* t;
        t = zinh; zinh = zoth; zoth = t;   t = zinl; zinl = zotl; zotl = t;
        t = zinTh; zinTh = zotTh; zotTh = t; t = zinTl; zinTl = zotTl; zotTl = t;
    }
    cudaEventRecord(ctx.evZ, s1);

    // --- main stream: attention chain ---
    // 3. attn1 = softmax(0.125 * q @ kl^T), fused GEMM+softmax, bf16 out
    hmma_sm1_k<<<dim3(1, 64, NH), 512, HSM>>>(qkvh, qkvl, 3*DM, DH, klh, kll, DH, (long)LM*DH,
        a1h, a1l, LM, (long)NT*LM, DH, 0.125f);

    // 5. attn3 logits
    hmma2_k<2><<<dim3(64, 2, NH), 256, HS2>>>(qlh, qll, DH, (long)LM*DH, qkvh + DM, qkvl + DM, 3*DM, DH,
        a3, NT, (long)LM*NT, DH, 1.f, nullptr, nullptr,
        NB16, NB16, 0, 0, NB16, NB16, 0, 0, 0, 0, 0.f, 1, 0);
    softmax8192<<<NH*LM, 256>>>(a3, a3h, a3l);

    // 8. t3 = attn3 @ v  (split-K=16); vT from s2
    cudaStreamWaitEvent(0, ctx.evVT, 0);
    hmma2_k<1><<<dim3(1, 2, NH*16), 128, HS1>>>(a3h, a3l, NT, (long)LM*NT, vth, vtl, NT, (long)DH*NT,
        t3p, DH, 0, NT, 1.f, nullptr, nullptr,
        NB16, NB16, 0, 0, NB16, NB16, 0, 0, 0, 0, 0.f, 16, (long)LM*DH);
    reduce_t3T<<<(NH*DH*LM + 255)/256, 256>>>(t3p, t3th, t3tl);

    // join pinv
    cudaStreamWaitEvent(0, ctx.evZ, 0);

    // 9. t4 = pinv @ t3
    hmma2_k<1><<<dim3(1, 2, NH), 128, HS1>>>(zinh, zinl, LM, HL, t3th, t3tl, LM, (long)DH*LM,
        F32N, 0, 0, LM, 1.f, nullptr, nullptr,
        NB16, NB16, 0, 0, t4th, t4tl, LM, (long)DH*LM, 0, 0, 0.f, 1, 0);

    // 10. outh = attn1 @ t4 + convres; emits bf16 hi/lo directly to th/tl
    cudaStreamWaitEvent(0, ctx.evConv, 0);
    hmma2_k<1><<<dim3(1, 64, NH), 128, HS1>>>(a1h, a1l, LM, (long)NT*LM, t4th, t4tl, LM, (long)DH*LM,
        F32N, DM, DH, LM, 1.f, nullptr, convres,
        th, tl, DM, DH, NB16, NB16, 0, 0, 0, 0, 0.f, 1, 0);

    // 12. enc = outh @ out_w + out_b + dense ; emits bf16 hi/lo to ench/encl
    cudaStreamWaitEvent(0, ctx.evW, 0);
    hmma2_k<2><<<dim3(4, 64, 1), 256, HS2>>>(th, tl, DM, 0, woth, wotl, DM, 0,
        enc, DM, 0, DM, 1.f, out_b, dense, ench, encl, DM, 0, NB16, NB16, 0, 0, 0, 0, 0.f, 1, 0);
    cudaEventRecord(ctx.evEnc, 0);

    // 13. q2 (main) ; k2 (s2, concurrent). enc bf16 in ench/encl.
    cudaStreamWaitEvent(s2, ctx.evEnc, 0);
    hmma2_k<2><<<dim3(2, 64, 1), 256, HS2, s2>>>(ench, encl, DM, 0, wkth, wktl, DM, 0,
        k2, ATTD, 0, DM, 1.f, nullptr, nullptr, NB16, NB16, 0, 0, NB16, NB16, 0, 0, 0, 0, 0.f, 1, 0);
    cudaEventRecord(ctx.evK2, s2);
    hmma2_k<2><<<dim3(2, 64, 1), 256, HS2>>>(ench, encl, DM, 0, wqth, wqtl, DM, 0,
        q2, ATTD, 0, DM, 1.f, nullptr, nullptr, NB16, NB16, 0, 0, NB16, NB16, 0, 0, 0, 0, 0.f, 1, 0);

    // 15. A_raw
    cudaStreamWaitEvent(0, ctx.evK2, 0);
    araw_k<<<NT, 256>>>(adj, q2, k2, Araw);

    // 16. alpha = softmax(A_raw)
    alpha_softmax_k<<<1, 1024>>>(Araw, alpha);

    // 17. final
    cudaStreamWaitEvent(0, ctx.evVal, 0);
    final_k<<<(NT*DM + 255)/256, 256>>>(val, enc, alpha, Araw, out);
}